// round 12
// baseline (speedup 1.0000x reference)
#include <cuda_runtime.h>
#include <cuda_fp16.h>
#include <math.h>

// ----------------------------------------------------------------------------
// EdgeBiasedAttention — v12: prep_hw folded into gemm_qkv as leading blocks
// with a release/acquire flag (3 launches total). GEMM/attention math = v11.
// B=32, N=512, D=256, H=8, HD=32
// ----------------------------------------------------------------------------

#define BATCH 32
#define NSEQ  512
#define DMODEL 256
#define NHEAD 8
#define HDIM  32
#define MROWS (BATCH * NSEQ)  // 16384

#define N_H8 (MROWS * DMODEL / 8)          // 524288
#define N_W8 (DMODEL * DMODEL / 8)         // 8192
#define N_E8 (BATCH * NSEQ * NSEQ / 8)     // 1048576
#define N_HW8 (N_H8 + 4 * N_W8)            // 557056
#define HW_BLOCKS 96

// fp16 scratch
__device__ __half g_h16 [MROWS * DMODEL];
__device__ __half g_q16 [MROWS * DMODEL];
__device__ __half g_k16 [MROWS * DMODEL];
__device__ __half g_v16 [MROWS * DMODEL];
__device__ __half g_ao16[MROWS * DMODEL];
__device__ __half g_em  [BATCH * NSEQ * NSEQ];   // masked edge (NaN = masked)
__device__ __half g_w16 [4 * DMODEL * DMODEL];   // Wq, Wk, Wv, Wo fp16
__device__ int    g_flag;                        // hw-prep completion counter

// ---------------- helpers ----------------
__device__ __forceinline__ void mma_f16(float c[4],
                                        unsigned a0, unsigned a1, unsigned a2, unsigned a3,
                                        unsigned b0, unsigned b1)
{
    asm volatile(
        "mma.sync.aligned.m16n8k16.row.col.f32.f16.f16.f32 "
        "{%0,%1,%2,%3}, {%4,%5,%6,%7}, {%8,%9}, {%0,%1,%2,%3};"
        : "+f"(c[0]), "+f"(c[1]), "+f"(c[2]), "+f"(c[3])
        : "r"(a0), "r"(a1), "r"(a2), "r"(a3), "r"(b0), "r"(b1));
}

__device__ __forceinline__ void cp16(void* sdst, const void* gsrc) {
    unsigned s = (unsigned)__cvta_generic_to_shared(sdst);
    asm volatile("cp.async.cg.shared.global [%0], [%1], 16;" :: "r"(s), "l"(gsrc));
}
#define CP_COMMIT() asm volatile("cp.async.commit_group;")
#define CP_WAIT0()  asm volatile("cp.async.wait_group 0;" ::: "memory")
#define CP_WAIT2()  asm volatile("cp.async.wait_group 2;" ::: "memory")

__device__ __forceinline__ void ldsm4(unsigned& r0, unsigned& r1, unsigned& r2, unsigned& r3,
                                      const __half* p)
{
    unsigned s = (unsigned)__cvta_generic_to_shared(p);
    asm volatile("ldmatrix.sync.aligned.m8n8.x4.shared.b16 {%0,%1,%2,%3}, [%4];"
                 : "=r"(r0), "=r"(r1), "=r"(r2), "=r"(r3) : "r"(s));
}
__device__ __forceinline__ void ldsm4t(unsigned& r0, unsigned& r1, unsigned& r2, unsigned& r3,
                                       const __half* p)
{
    unsigned s = (unsigned)__cvta_generic_to_shared(p);
    asm volatile("ldmatrix.sync.aligned.m8n8.x4.trans.shared.b16 {%0,%1,%2,%3}, [%4];"
                 : "=r"(r0), "=r"(r1), "=r"(r2), "=r"(r3) : "r"(s));
}

__device__ __forceinline__ uint4 pack8(float4 a, float4 b) {
    uint4 o;
    __half2 h0 = __floats2half2_rn(a.x, a.y);
    __half2 h1 = __floats2half2_rn(a.z, a.w);
    __half2 h2 = __floats2half2_rn(b.x, b.y);
    __half2 h3 = __floats2half2_rn(b.z, b.w);
    o.x = *(unsigned*)&h0; o.y = *(unsigned*)&h1;
    o.z = *(unsigned*)&h2; o.w = *(unsigned*)&h3;
    return o;
}

// ----------------------------------------------------------------------------
// GEMM core: 128x128 tile, BK=32, 4-stage cp.async pipeline, ldmatrix frags.
// Dynamic smem: Xs[4][128*40], Ws[4][128*40]  (81920 B)
// ----------------------------------------------------------------------------
#define GSTG (128 * 40)
#define GEMM_SMEM_BYTES (8 * GSTG * 2)

#define GEMM_BODY(X, W, ACC)                                                         \
    __half* Xs = gsm;                                                                \
    __half* Ws = gsm + 4 * GSTG;                                                     \
    const int srow = t >> 2, sc = t & 3;                                             \
    _Pragma("unroll")                                                                \
    for (int st = 0; st < 3; ++st) {                                                 \
        int k0 = st * 32;                                                            \
        _Pragma("unroll")                                                            \
        for (int i = 0; i < 2; ++i) {                                                \
            int row = srow + i * 64;                                                 \
            cp16(Xs + st * GSTG + row * 40 + sc * 8, X + (size_t)(m0 + row) * 256 + k0 + sc * 8); \
            cp16(Ws + st * GSTG + row * 40 + sc * 8, W + (size_t)(n0 + row) * 256 + k0 + sc * 8); \
        }                                                                            \
        CP_COMMIT();                                                                 \
    }                                                                                \
    const int arow = wm + (lane & 7) + ((lane >> 3) & 1) * 8;                        \
    const int acol = ((lane >> 4) << 3);                                             \
    const int brow = wn + ((lane >> 4) << 3) + (lane & 7);                           \
    const int bcol = ((lane >> 3) & 1) << 3;                                         \
    for (int p = 0; p < 8; ++p) {                                                    \
        CP_WAIT2();                                                                  \
        __syncthreads();                                                             \
        if (p < 5) {                                                                 \
            int k0 = (p + 3) * 32, buf = (p + 3) & 3;                                \
            _Pragma("unroll")                                                        \
            for (int i = 0; i < 2; ++i) {                                            \
                int row = srow + i * 64;                                             \
                cp16(Xs + buf * GSTG + row * 40 + sc * 8, X + (size_t)(m0 + row) * 256 + k0 + sc * 8); \
                cp16(Ws + buf * GSTG + row * 40 + sc * 8, W + (size_t)(n0 + row) * 256 + k0 + sc * 8); \
            }                                                                        \
        }                                                                            \
        CP_COMMIT();                                                                 \
        const __half* Xb = Xs + (p & 3) * GSTG;                                      \
        const __half* Wb = Ws + (p & 3) * GSTG;                                      \
        _Pragma("unroll")                                                            \
        for (int kc = 0; kc < 2; ++kc) {                                             \
            unsigned a[4][4], bb[4][2];                                              \
            _Pragma("unroll")                                                        \
            for (int mt = 0; mt < 4; ++mt)                                           \
                ldsm4(a[mt][0], a[mt][1], a[mt][2], a[mt][3],                        \
                      Xb + (arow + mt * 16) * 40 + kc * 16 + acol);                  \
            _Pragma("unroll")                                                        \
            for (int np = 0; np < 2; ++np)                                           \
                ldsm4(bb[np * 2][0], bb[np * 2][1], bb[np * 2 + 1][0], bb[np * 2 + 1][1], \
                      Wb + (brow + np * 16) * 40 + kc * 16 + bcol);                  \
            _Pragma("unroll")                                                        \
            for (int mt = 0; mt < 4; ++mt)                                           \
                _Pragma("unroll")                                                    \
                for (int nt = 0; nt < 4; ++nt)                                       \
                    mma_f16(ACC[mt][nt], a[mt][0], a[mt][1], a[mt][2], a[mt][3],     \
                            bb[nt][0], bb[nt][1]);                                   \
        }                                                                            \
    }

// ----------------------------------------------------------------------------
// Fused QKV GEMM + ALL preprocessing (em + h/W conversion).
// grid (6, 176):
//   by <  32 : em-prep streaming blocks (192) — no dependencies
//   by <  48 : h/W fp16 conversion blocks (96) — signal g_flag when done
//   by >= 48 : 128x128 gemm tiles (768) — wait for g_flag >= 96 before staging
// bx>>1 selects Q/K/V; (bx&1)*128 is n-offset. Q output pre-scaled.
// ----------------------------------------------------------------------------
__global__ __launch_bounds__(256, 2) void gemm_qkv(
    const float* __restrict__ hf, const float* __restrict__ Wqf,
    const float* __restrict__ Wkf, const float* __restrict__ Wvf,
    const float* __restrict__ Wof,
    const __half* __restrict__ X, const __half* __restrict__ Wcat,
    __half* __restrict__ Qd, __half* __restrict__ Kd, __half* __restrict__ Vd,
    const float* __restrict__ edge, const int* __restrict__ mask,
    __half* __restrict__ em, __half* __restrict__ h16w, __half* __restrict__ w16w)
{
    extern __shared__ __half gsm[];
    const int t = threadIdx.x;

    if (blockIdx.y < 32) {
        // ---- em preprocessing block (pure streaming) ----
        const float QNAN = __int_as_float(0x7fc00000);
        int chunk = blockIdx.y * 6 + blockIdx.x;             // 0..191
        for (int j = chunk * 256 + t; j < N_E8; j += 192 * 256) {
            const float4* es = (const float4*)edge + (size_t)j * 2;
            const int4*   ms = (const int4*)mask + (size_t)j * 2;
            float4 e0 = es[0], e1 = es[1];
            int4   m0v = ms[0], m1v = ms[1];
            float4 f0 = make_float4(m0v.x ? e0.x : QNAN, m0v.y ? e0.y : QNAN,
                                    m0v.z ? e0.z : QNAN, m0v.w ? e0.w : QNAN);
            float4 f1 = make_float4(m1v.x ? e1.x : QNAN, m1v.y ? e1.y : QNAN,
                                    m1v.z ? e1.z : QNAN, m1v.w ? e1.w : QNAN);
            ((uint4*)em)[j] = pack8(f0, f1);
        }
        return;
    }

    if (blockIdx.y < 48) {
        // ---- h/W fp16 conversion block; signals g_flag ----
        int chunk = (blockIdx.y - 32) * 6 + blockIdx.x;      // 0..95
        for (int i = chunk * 256 + t; i < N_HW8; i += HW_BLOCKS * 256) {
            if (i < N_H8) {
                const float4* s = (const float4*)hf + (size_t)i * 2;
                ((uint4*)h16w)[i] = pack8(s[0], s[1]);
            } else {
                int j = i - N_H8;
                int which = j >> 13, off = j & (N_W8 - 1);
                const float* W = which == 0 ? Wqf : which == 1 ? Wkf
                               : which == 2 ? Wvf : Wof;
                const float4* s = (const float4*)W + (size_t)off * 2;
                ((uint4*)w16w)[(size_t)which * N_W8 + off] = pack8(s[0], s[1]);
            }
        }
        __threadfence();
        __syncthreads();
        if (t == 0) atomicAdd(&g_flag, 1);
        return;
    }

    // ---- gemm tile: wait for h/W conversion (wave-1 preps have lower bids) --
    if (t == 0) {
        while (atomicAdd(&g_flag, 0) < HW_BLOCKS) __nanosleep(64);
    }
    __syncthreads();
    __threadfence();

    const int warp = t >> 5, lane = t & 31;
    const int g = lane >> 2, l = lane & 3;
    const int m0 = (blockIdx.y - 48) * 128, n0 = blockIdx.x * 128;
    const int wm = (warp >> 2) * 64, wn = (warp & 3) * 32;
    const int which = blockIdx.x >> 1;
    __half* dst = which == 0 ? Qd : which == 1 ? Kd : Vd;
    const int nloc = n0 & 255;
    const float oscale = (which == 0) ? 0.17677669529663687f * 1.4426950408889634f : 1.0f;

    float acc[4][4][4];
#pragma unroll
    for (int mt = 0; mt < 4; ++mt)
#pragma unroll
        for (int nt = 0; nt < 4; ++nt)
#pragma unroll
            for (int i = 0; i < 4; ++i) acc[mt][nt][i] = 0.f;

    GEMM_BODY(X, Wcat, acc)

#pragma unroll
    for (int mt = 0; mt < 4; ++mt) {
#pragma unroll
        for (int nt = 0; nt < 4; ++nt) {
            int r = m0 + wm + mt * 16 + g;
            int c = nloc + wn + nt * 8 + 2 * l;
            *(__half2*)(dst + (size_t)r * 256 + c) =
                __floats2half2_rn(acc[mt][nt][0] * oscale, acc[mt][nt][1] * oscale);
            *(__half2*)(dst + (size_t)(r + 8) * 256 + c) =
                __floats2half2_rn(acc[mt][nt][2] * oscale, acc[mt][nt][3] * oscale);
        }
    }
}

// Output GEMM: fp32 out, 128x128 tiles, grid (2, 128)
__global__ __launch_bounds__(256, 2) void gemm_out(const __half* __restrict__ X,
                                                   const __half* __restrict__ W,
                                                   float* __restrict__ C)
{
    extern __shared__ __half gsm[];

    const int t = threadIdx.x, warp = t >> 5, lane = t & 31;
    const int g = lane >> 2, l = lane & 3;
    const int m0 = blockIdx.y * 128, n0 = blockIdx.x * 128;
    const int wm = (warp >> 2) * 64, wn = (warp & 3) * 32;

    float acc[4][4][4];
#pragma unroll
    for (int mt = 0; mt < 4; ++mt)
#pragma unroll
        for (int nt = 0; nt < 4; ++nt)
#pragma unroll
            for (int i = 0; i < 4; ++i) acc[mt][nt][i] = 0.f;

    GEMM_BODY(X, W, acc)

#pragma unroll
    for (int mt = 0; mt < 4; ++mt) {
#pragma unroll
        for (int nt = 0; nt < 4; ++nt) {
            int r = m0 + wm + mt * 16 + g;
            int c = n0 + wn + nt * 8 + 2 * l;
            *(float2*)(C + (size_t)r * 256 + c)       = make_float2(acc[mt][nt][0], acc[mt][nt][1]);
            *(float2*)(C + (size_t)(r + 8) * 256 + c) = make_float2(acc[mt][nt][2], acc[mt][nt][3]);
        }
    }
}

// ----------------------------------------------------------------------------
// Attention (fp16) — unchanged from v11 (occ 5 blocks/SM).
// ----------------------------------------------------------------------------
#define KLDH 40   // K/V row stride halves (80B) -> conflict-free
#define ELDH 72   // em row stride halves (144B) -> conflict-free

__global__ __launch_bounds__(128, 5) void attn_f16(
    const __half* __restrict__ Qh, const __half* __restrict__ Kh,
    const __half* __restrict__ Vh, const __half* __restrict__ em,
    const float* __restrict__ We, __half* __restrict__ AOh)
{
    __shared__ __half Ks[2][64 * KLDH];
    __shared__ __half Vs[2][64 * KLDH];
    __shared__ __half Es[2][64 * ELDH];

    const int t = threadIdx.x, warp = t >> 5, lane = t & 31;
    const int g = lane >> 2, l = lane & 3;
    const int bh = blockIdx.y;
    const int b  = bh >> 3, hh = bh & 7;
    const int q0 = blockIdx.x * 64;
    const size_t bN = (size_t)b * NSEQ;
    const int R0 = warp * 16 + g;
    const float we = We[hh] * 1.4426950408889634f;   // log2 domain

    const int arow = warp * 16 + (lane & 7) + ((lane >> 3) & 1) * 8;
    const int acol = ((lane >> 4) << 3);
    const int krow = (lane & 7);
    const int kcol = ((lane >> 3) << 3);

#pragma unroll
    for (int i = 0; i < 2; ++i) {
        int idx = t + i * 128;
        int row = idx >> 2, c = idx & 3;
        uint4 v = *(const uint4*)(Qh + ((bN + q0 + row) * DMODEL) + hh * HDIM + c * 8);
        *(uint4*)&Ks[0][row * KLDH + c * 8] = v;
    }
    __syncthreads();

    unsigned qa[2][4];
    ldsm4(qa[0][0], qa[0][1], qa[0][2], qa[0][3], Ks[0] + arow * KLDH + acol);
    ldsm4(qa[1][0], qa[1][1], qa[1][2], qa[1][3], Ks[0] + arow * KLDH + 16 + acol);
    __syncthreads();

    float m0r = -1e30f, m1r = -1e30f, l0r = 0.f, l1r = 0.f;
    float o[4][4];
#pragma unroll
    for (int nt = 0; nt < 4; ++nt)
#pragma unroll
        for (int i = 0; i < 4; ++i) o[nt][i] = 0.f;

    const int kv_row = t >> 2, kv_c = t & 3;
    const int em_row = t >> 3, em_c = t & 7;

#pragma unroll
    for (int i = 0; i < 2; ++i) {
        int row = kv_row + i * 32;
        cp16(&Ks[0][row * KLDH + kv_c * 8], Kh + (bN + row) * DMODEL + hh * HDIM + kv_c * 8);
        cp16(&Vs[0][row * KLDH + kv_c * 8], Vh + (bN + row) * DMODEL + hh * HDIM + kv_c * 8);
    }
#pragma unroll
    for (int i = 0; i < 4; ++i) {
        int row = em_row + i * 16;
        cp16(&Es[0][row * ELDH + em_c * 8], em + ((bN + q0 + row) * NSEQ) + em_c * 8);
    }
    CP_COMMIT();

    for (int it = 0; it < 8; ++it) {
        CP_WAIT0();
        __syncthreads();
        if (it < 7) {
            int jt = (it + 1) * 64, buf = (it + 1) & 1;
#pragma unroll
            for (int i = 0; i < 2; ++i) {
                int row = kv_row + i * 32;
                cp16(&Ks[buf][row * KLDH + kv_c * 8],
                     Kh + (bN + jt + row) * DMODEL + hh * HDIM + kv_c * 8);
                cp16(&Vs[buf][row * KLDH + kv_c * 8],
                     Vh + (bN + jt + row) * DMODEL + hh * HDIM + kv_c * 8);
            }
#pragma unroll
            for (int i = 0; i < 4; ++i) {
                int row = em_row + i * 16;
                cp16(&Es[buf][row * ELDH + em_c * 8],
                     em + ((bN + q0 + row) * NSEQ) + jt + em_c * 8);
            }
        }
        CP_COMMIT();

        const __half* Kb = Ks[it & 1];
        const __half* Eb = Es[it & 1];
        const __half* Vb = Vs[it & 1];

        float s[8][4];
#pragma unroll
        for (int nt = 0; nt < 8; ++nt) {
            s[nt][0] = s[nt][1] = s[nt][2] = s[nt][3] = 0.f;
            unsigned b0, b1, b2, b3;
            ldsm4(b0, b1, b2, b3, Kb + (8 * nt + krow) * KLDH + kcol);
            mma_f16(s[nt], qa[0][0], qa[0][1], qa[0][2], qa[0][3], b0, b1);
            mma_f16(s[nt], qa[1][0], qa[1][1], qa[1][2], qa[1][3], b2, b3);
        }

        float mn0 = m0r, mn1 = m1r;
#pragma unroll
        for (int i = 0; i < 4; ++i) {
            unsigned e0, e1, e2, e3;
            ldsm4(e0, e1, e2, e3, Eb + arow * ELDH + i * 16 + acol);
            float2 f0 = __half22float2(*(__half2*)&e0);
            float2 f1 = __half22float2(*(__half2*)&e1);
            float2 f2 = __half22float2(*(__half2*)&e2);
            float2 f3 = __half22float2(*(__half2*)&e3);
            int n0i = 2 * i, n1i = 2 * i + 1;
            s[n0i][0] = fmaxf(fmaf(we, f0.x, s[n0i][0]), -1e30f);
            s[n0i][1] = fmaxf(fmaf(we, f0.y, s[n0i][1]), -1e30f);
            s[n0i][2] = fmaxf(fmaf(we, f1.x, s[n0i][2]), -1e30f);
            s[n0i][3] = fmaxf(fmaf(we, f1.y, s[n0i][3]), -1e30f);
            s[n1i][0] = fmaxf(fmaf(we, f2.x, s[n1i][0]), -1e30f);
            s[n1i][1] = fmaxf(fmaf(we, f2.y, s[n1i][1]), -1e30f);
            s[n1i][2] = fmaxf(fmaf(we, f3.x, s[n1i][2]), -1e30f);
            s[n1i][3] = fmaxf(fmaf(we, f3.y, s[n1i][3]), -1e30f);
            mn0 = fmaxf(mn0, fmaxf(fmaxf(s[n0i][0], s[n0i][1]), fmaxf(s[n1i][0], s[n1i][1])));
            mn1 = fmaxf(mn1, fmaxf(fmaxf(s[n0i][2], s[n0i][3]), fmaxf(s[n1i][2], s[n1i][3])));
        }
        mn0 = fmaxf(mn0, __shfl_xor_sync(0xffffffff, mn0, 1));
        mn0 = fmaxf(mn0, __shfl_xor_sync(0xffffffff, mn0, 2));
        mn1 = fmaxf(mn1, __shfl_xor_sync(0xffffffff, mn1, 1));
        mn1 = fmaxf(mn1, __shfl_xor_sync(0xffffffff, mn1, 2));

        float corr0 = exp2f(m0r - mn0);
        float corr1 = exp2f(m1r - mn1);
        m0r = mn0; m1r = mn1;

        unsigned ph[8][2];
        float ps0 = 0.f, ps1 = 0.f;
#pragma unroll
        for (int nt = 0; nt < 8; ++nt) {
            __half2 x01 = __floats2half2_rn(s[nt][0] - mn0, s[nt][1] - mn0);
            __half2 x23 = __floats2half2_rn(s[nt][2] - mn1, s[nt][3] - mn1);
            __half2 p01 = h2exp2(x01);
            __half2 p23 = h2exp2(x23);
            ph[nt][0] = *(unsigned*)&p01;
            ph[nt][1] = *(unsigned*)&p23;
            float2 f01 = __half22float2(p01);
            float2 f23 = __half22float2(p23);
            ps0 += f01.x + f01.y;
            ps1 += f23.x + f23.y;
        }
        ps0 += __shfl_xor_sync(0xffffffff, ps0, 1);
        ps0 += __shfl_xor_sync(0xffffffff, ps0, 2);
        ps1 += __shfl_xor_sync(0xffffffff, ps1, 1);
        ps1 += __shfl_xor_sync(0xffffffff, ps1, 2);
        l0r = l0r * corr0 + ps0;
        l1r = l1r * corr1 + ps1;

#pragma unroll
        for (int nt = 0; nt < 4; ++nt) {
            o[nt][0] *= corr0; o[nt][1] *= corr0;
            o[nt][2] *= corr1; o[nt][3] *= corr1;
        }

        const int vkey = ((lane >> 3) & 1) << 3;
        const int vd   = ((lane >> 4) & 1) << 3;
        const int vr   = lane & 7;
#pragma unroll
        for (int kc = 0; kc < 4; ++kc) {
            unsigned a0 = ph[2 * kc][0];
            unsigned a1 = ph[2 * kc][1];
            unsigned a2 = ph[2 * kc + 1][0];
            unsigned a3 = ph[2 * kc + 1][1];
            unsigned v0, v1, v2, v3, v4, v5, v6, v7;
            const __half* basep = Vb + (16 * kc + vkey + vr) * KLDH + vd;
            ldsm4t(v0, v1, v2, v3, basep);
            ldsm4t(v4, v5, v6, v7, basep + 16);
            mma_f16(o[0], a0, a1, a2, a3, v0, v1);
            mma_f16(o[1], a0, a1, a2, a3, v2, v3);
            mma_f16(o[2], a0, a1, a2, a3, v4, v5);
            mma_f16(o[3], a0, a1, a2, a3, v6, v7);
        }
    }

    const float inv0 = 1.0f / l0r;
    const float inv1 = 1.0f / l1r;
#pragma unroll
    for (int nt = 0; nt < 4; ++nt) {
        int c = hh * HDIM + nt * 8 + 2 * l;
        *(__half2*)(AOh + (bN + q0 + R0) * DMODEL + c) =
            __floats2half2_rn(o[nt][0] * inv0, o[nt][1] * inv0);
        *(__half2*)(AOh + (bN + q0 + R0 + 8) * DMODEL + c) =
            __floats2half2_rn(o[nt][2] * inv1, o[nt][3] * inv1);
    }
}

// ----------------------------------------------------------------------------
// launch
// ----------------------------------------------------------------------------
extern "C" void kernel_launch(void* const* d_in, const int* in_sizes, int n_in,
                              void* d_out, int out_size)
{
    const float* h    = (const float*)d_in[0];
    const float* edge = (const float*)d_in[1];
    const int*   mask = (const int*)  d_in[2];
    const float* Wq   = (const float*)d_in[3];
    const float* Wk   = (const float*)d_in[4];
    const float* Wv   = (const float*)d_in[5];
    const float* We   = (const float*)d_in[6];
    const float* Wo   = (const float*)d_in[7];
    float* out = (float*)d_out;

    __half *h16, *q16, *k16, *v16, *ao16, *emh, *w16;
    cudaGetSymbolAddress((void**)&h16,  g_h16);
    cudaGetSymbolAddress((void**)&q16,  g_q16);
    cudaGetSymbolAddress((void**)&k16,  g_k16);
    cudaGetSymbolAddress((void**)&v16,  g_v16);
    cudaGetSymbolAddress((void**)&ao16, g_ao16);
    cudaGetSymbolAddress((void**)&emh,  g_em);
    cudaGetSymbolAddress((void**)&w16,  g_w16);

    cudaFuncSetAttribute(gemm_qkv, cudaFuncAttributeMaxDynamicSharedMemorySize, GEMM_SMEM_BYTES);
    cudaFuncSetAttribute(gemm_out, cudaFuncAttributeMaxDynamicSharedMemorySize, GEMM_SMEM_BYTES);

    // by<32: em-prep; by in [32,48): h/W conversion (signals flag);
    // by>=48: 128x128 gemm tiles (wait on flag).
    gemm_qkv<<<dim3(6, 176), 256, GEMM_SMEM_BYTES>>>(
        h, Wq, Wk, Wv, Wo,
        h16, w16, q16, k16, v16, edge, mask, emh, h16, w16);

    attn_f16<<<dim3(NSEQ / 64, BATCH * NHEAD), 128>>>(q16, k16, v16, emh, We, ao16);

    gemm_out<<<dim3(2, MROWS / 128), 256, GEMM_SMEM_BYTES>>>(ao16, w16 + 3 * DMODEL * DMODEL, out);
}

// round 13
// speedup vs baseline: 1.0192x; 1.0192x over previous
#include <cuda_runtime.h>
#include <cuda_fp16.h>
#include <math.h>

// ----------------------------------------------------------------------------
// EdgeBiasedAttention — v13: v11 base; gemm_out merged into the attention
// launch as trailing flag-gated blocks (attention is never gated).
// B=32, N=512, D=256, H=8, HD=32
// ----------------------------------------------------------------------------

#define BATCH 32
#define NSEQ  512
#define DMODEL 256
#define NHEAD 8
#define HDIM  32
#define MROWS (BATCH * NSEQ)  // 16384

#define N_H8 (MROWS * DMODEL / 8)          // 524288
#define N_W8 (DMODEL * DMODEL / 8)         // 8192
#define N_E8 (BATCH * NSEQ * NSEQ / 8)     // 1048576
#define N_HW8 (N_H8 + 4 * N_W8)            // 557056

#define ATTN_BLOCKS 2048
#define OUT_BLOCKS  1024                   // 256 row-groups x 4 col-tiles

// fp16 scratch
__device__ __half g_h16 [MROWS * DMODEL];
__device__ __half g_q16 [MROWS * DMODEL];
__device__ __half g_k16 [MROWS * DMODEL];
__device__ __half g_v16 [MROWS * DMODEL];
__device__ __half g_ao16[MROWS * DMODEL];
__device__ __half g_em  [BATCH * NSEQ * NSEQ];   // masked edge (NaN = masked)
__device__ __half g_w16 [4 * DMODEL * DMODEL];   // Wq, Wk, Wv, Wo fp16
__device__ int    g_done[256];                   // per-64-row-group AO completion

// ---------------- helpers ----------------
__device__ __forceinline__ void mma_f16(float c[4],
                                        unsigned a0, unsigned a1, unsigned a2, unsigned a3,
                                        unsigned b0, unsigned b1)
{
    asm volatile(
        "mma.sync.aligned.m16n8k16.row.col.f32.f16.f16.f32 "
        "{%0,%1,%2,%3}, {%4,%5,%6,%7}, {%8,%9}, {%0,%1,%2,%3};"
        : "+f"(c[0]), "+f"(c[1]), "+f"(c[2]), "+f"(c[3])
        : "r"(a0), "r"(a1), "r"(a2), "r"(a3), "r"(b0), "r"(b1));
}

__device__ __forceinline__ void cp16(void* sdst, const void* gsrc) {
    unsigned s = (unsigned)__cvta_generic_to_shared(sdst);
    asm volatile("cp.async.cg.shared.global [%0], [%1], 16;" :: "r"(s), "l"(gsrc));
}
#define CP_COMMIT() asm volatile("cp.async.commit_group;")
#define CP_WAIT0()  asm volatile("cp.async.wait_group 0;" ::: "memory")
#define CP_WAIT2()  asm volatile("cp.async.wait_group 2;" ::: "memory")

__device__ __forceinline__ void ldsm4(unsigned& r0, unsigned& r1, unsigned& r2, unsigned& r3,
                                      const __half* p)
{
    unsigned s = (unsigned)__cvta_generic_to_shared(p);
    asm volatile("ldmatrix.sync.aligned.m8n8.x4.shared.b16 {%0,%1,%2,%3}, [%4];"
                 : "=r"(r0), "=r"(r1), "=r"(r2), "=r"(r3) : "r"(s));
}
__device__ __forceinline__ void ldsm4t(unsigned& r0, unsigned& r1, unsigned& r2, unsigned& r3,
                                       const __half* p)
{
    unsigned s = (unsigned)__cvta_generic_to_shared(p);
    asm volatile("ldmatrix.sync.aligned.m8n8.x4.trans.shared.b16 {%0,%1,%2,%3}, [%4];"
                 : "=r"(r0), "=r"(r1), "=r"(r2), "=r"(r3) : "r"(s));
}

__device__ __forceinline__ uint4 pack8(float4 a, float4 b) {
    uint4 o;
    __half2 h0 = __floats2half2_rn(a.x, a.y);
    __half2 h1 = __floats2half2_rn(a.z, a.w);
    __half2 h2 = __floats2half2_rn(b.x, b.y);
    __half2 h3 = __floats2half2_rn(b.z, b.w);
    o.x = *(unsigned*)&h0; o.y = *(unsigned*)&h1;
    o.z = *(unsigned*)&h2; o.w = *(unsigned*)&h3;
    return o;
}

// ---------------- preprocessing: h + weights (v11) ----------------
__global__ __launch_bounds__(256) void prep_hw(
    const float* __restrict__ h,
    const float* __restrict__ Wq, const float* __restrict__ Wk,
    const float* __restrict__ Wv, const float* __restrict__ Wo,
    __half* __restrict__ h16, __half* __restrict__ w16)
{
    int i = blockIdx.x * 256 + threadIdx.x;
    if (i < N_H8) {
        const float4* s = (const float4*)h + (size_t)i * 2;
        ((uint4*)h16)[i] = pack8(s[0], s[1]);
    } else if (i < N_HW8) {
        int j = i - N_H8;
        int which = j >> 13, off = j & (N_W8 - 1);
        const float* W = which == 0 ? Wq : which == 1 ? Wk : which == 2 ? Wv : Wo;
        const float4* s = (const float4*)W + (size_t)off * 2;
        ((uint4*)w16)[(size_t)which * N_W8 + off] = pack8(s[0], s[1]);
    }
}

// ----------------------------------------------------------------------------
// GEMM core: 128x128 tile, BK=32, 4-stage cp.async pipeline (v11).
// ----------------------------------------------------------------------------
#define GSTG (128 * 40)
#define GEMM_SMEM_BYTES (8 * GSTG * 2)

#define GEMM_BODY(X, W, ACC)                                                         \
    __half* Xs = gsm;                                                                \
    __half* Ws = gsm + 4 * GSTG;                                                     \
    const int srow = t >> 2, sc = t & 3;                                             \
    _Pragma("unroll")                                                                \
    for (int st = 0; st < 3; ++st) {                                                 \
        int k0 = st * 32;                                                            \
        _Pragma("unroll")                                                            \
        for (int i = 0; i < 2; ++i) {                                                \
            int row = srow + i * 64;                                                 \
            cp16(Xs + st * GSTG + row * 40 + sc * 8, X + (size_t)(m0 + row) * 256 + k0 + sc * 8); \
            cp16(Ws + st * GSTG + row * 40 + sc * 8, W + (size_t)(n0 + row) * 256 + k0 + sc * 8); \
        }                                                                            \
        CP_COMMIT();                                                                 \
    }                                                                                \
    const int arow = wm + (lane & 7) + ((lane >> 3) & 1) * 8;                        \
    const int acol = ((lane >> 4) << 3);                                             \
    const int brow = wn + ((lane >> 4) << 3) + (lane & 7);                           \
    const int bcol = ((lane >> 3) & 1) << 3;                                         \
    for (int p = 0; p < 8; ++p) {                                                    \
        CP_WAIT2();                                                                  \
        __syncthreads();                                                             \
        if (p < 5) {                                                                 \
            int k0 = (p + 3) * 32, buf = (p + 3) & 3;                                \
            _Pragma("unroll")                                                        \
            for (int i = 0; i < 2; ++i) {                                            \
                int row = srow + i * 64;                                             \
                cp16(Xs + buf * GSTG + row * 40 + sc * 8, X + (size_t)(m0 + row) * 256 + k0 + sc * 8); \
                cp16(Ws + buf * GSTG + row * 40 + sc * 8, W + (size_t)(n0 + row) * 256 + k0 + sc * 8); \
            }                                                                        \
        }                                                                            \
        CP_COMMIT();                                                                 \
        const __half* Xb = Xs + (p & 3) * GSTG;                                      \
        const __half* Wb = Ws + (p & 3) * GSTG;                                      \
        _Pragma("unroll")                                                            \
        for (int kc = 0; kc < 2; ++kc) {                                             \
            unsigned a[4][4], bb[4][2];                                              \
            _Pragma("unroll")                                                        \
            for (int mt = 0; mt < 4; ++mt)                                           \
                ldsm4(a[mt][0], a[mt][1], a[mt][2], a[mt][3],                        \
                      Xb + (arow + mt * 16) * 40 + kc * 16 + acol);                  \
            _Pragma("unroll")                                                        \
            for (int np = 0; np < 2; ++np)                                           \
                ldsm4(bb[np * 2][0], bb[np * 2][1], bb[np * 2 + 1][0], bb[np * 2 + 1][1], \
                      Wb + (brow + np * 16) * 40 + kc * 16 + bcol);                  \
            _Pragma("unroll")                                                        \
            for (int mt = 0; mt < 4; ++mt)                                           \
                _Pragma("unroll")                                                    \
                for (int nt = 0; nt < 4; ++nt)                                       \
                    mma_f16(ACC[mt][nt], a[mt][0], a[mt][1], a[mt][2], a[mt][3],     \
                            bb[nt][0], bb[nt][1]);                                   \
        }                                                                            \
    }

// Fused QKV GEMM + em preprocessing (v11). grid (6, 160):
// by<32: em-prep streaming; by>=32: 128x128 gemm tiles.
__global__ __launch_bounds__(256, 2) void gemm_qkv(
    const __half* __restrict__ X, const __half* __restrict__ Wcat,
    __half* __restrict__ Qd, __half* __restrict__ Kd, __half* __restrict__ Vd,
    const float* __restrict__ edge, const int* __restrict__ mask,
    __half* __restrict__ em)
{
    extern __shared__ __half gsm[];
    const int t = threadIdx.x;

    if (blockIdx.y < 32) {
        const float QNAN = __int_as_float(0x7fc00000);
        int chunk = blockIdx.y * 6 + blockIdx.x;             // 0..191
        for (int j = chunk * 256 + t; j < N_E8; j += 192 * 256) {
            const float4* es = (const float4*)edge + (size_t)j * 2;
            const int4*   ms = (const int4*)mask + (size_t)j * 2;
            float4 e0 = es[0], e1 = es[1];
            int4   m0v = ms[0], m1v = ms[1];
            float4 f0 = make_float4(m0v.x ? e0.x : QNAN, m0v.y ? e0.y : QNAN,
                                    m0v.z ? e0.z : QNAN, m0v.w ? e0.w : QNAN);
            float4 f1 = make_float4(m1v.x ? e1.x : QNAN, m1v.y ? e1.y : QNAN,
                                    m1v.z ? e1.z : QNAN, m1v.w ? e1.w : QNAN);
            ((uint4*)em)[j] = pack8(f0, f1);
        }
        return;
    }

    const int warp = t >> 5, lane = t & 31;
    const int g = lane >> 2, l = lane & 3;
    const int m0 = (blockIdx.y - 32) * 128, n0 = blockIdx.x * 128;
    const int wm = (warp >> 2) * 64, wn = (warp & 3) * 32;
    const int which = blockIdx.x >> 1;
    __half* dst = which == 0 ? Qd : which == 1 ? Kd : Vd;
    const int nloc = n0 & 255;
    const float oscale = (which == 0) ? 0.17677669529663687f * 1.4426950408889634f : 1.0f;

    float acc[4][4][4];
#pragma unroll
    for (int mt = 0; mt < 4; ++mt)
#pragma unroll
        for (int nt = 0; nt < 4; ++nt)
#pragma unroll
            for (int i = 0; i < 4; ++i) acc[mt][nt][i] = 0.f;

    GEMM_BODY(X, Wcat, acc)

#pragma unroll
    for (int mt = 0; mt < 4; ++mt) {
#pragma unroll
        for (int nt = 0; nt < 4; ++nt) {
            int r = m0 + wm + mt * 16 + g;
            int c = nloc + wn + nt * 8 + 2 * l;
            *(__half2*)(dst + (size_t)r * 256 + c) =
                __floats2half2_rn(acc[mt][nt][0] * oscale, acc[mt][nt][1] * oscale);
            *(__half2*)(dst + (size_t)(r + 8) * 256 + c) =
                __floats2half2_rn(acc[mt][nt][2] * oscale, acc[mt][nt][3] * oscale);
        }
    }
}

// ----------------------------------------------------------------------------
// Merged attention + output GEMM, one launch (128 threads/block, occ 5).
//   blockIdx.x <  2048 : attention block (never gated); signals g_done[group]
//   blockIdx.x >= 2048 : output-GEMM 64x64 tile; waits g_done[group] >= 8
// Dynamic smem: 38912 B (attn layout; out path uses 20480 B of it).
// ----------------------------------------------------------------------------
#define KLDH 40   // K/V row stride halves (80B) -> conflict-free
#define ELDH 72   // em row stride halves (144B) -> conflict-free
#define ATTN_SMEM_BYTES 38912

__global__ __launch_bounds__(128, 5) void attn_out(
    const __half* __restrict__ Qh, const __half* __restrict__ Kh,
    const __half* __restrict__ Vh, const __half* __restrict__ em,
    const float* __restrict__ We, __half* __restrict__ AOh,
    const __half* __restrict__ Wo16, float* __restrict__ Cout)
{
    extern __shared__ __half dsm[];
    const int t = threadIdx.x, warp = t >> 5, lane = t & 31;
    const int g = lane >> 2, l = lane & 3;

    if (blockIdx.x >= ATTN_BLOCKS) {
        // ================= output GEMM tile: 64x64, K=256 =================
        const int id2 = blockIdx.x - ATTN_BLOCKS;     // 0..1023
        const int grp = id2 >> 2;                     // 64-row group 0..255
        const int m0 = grp * 64;
        const int n0 = (id2 & 3) * 64;

        // wait for the 8 attention blocks feeding rows [m0, m0+64)
        if (t == 0) {
            while (atomicAdd(&g_done[grp], 0) < 8) __nanosleep(128);
        }
        __syncthreads();
        __threadfence();

        __half* Xs0 = dsm;            // 2 x 64x40 = 5120 halves
        __half* Ws0 = dsm + 5120;     // 2 x 64x40

        const int wm = (warp >> 1) * 32, wn = (warp & 1) * 32;

        float acc[2][4][4];
#pragma unroll
        for (int mt = 0; mt < 2; ++mt)
#pragma unroll
            for (int nt = 0; nt < 4; ++nt)
#pragma unroll
                for (int i = 0; i < 4; ++i) acc[mt][nt][i] = 0.f;

        // prologue: stage panel 0
#pragma unroll
        for (int i = 0; i < 2; ++i) {
            int idx = t + i * 128, row = idx >> 2, c = idx & 3;
            cp16(Xs0 + row * 40 + c * 8, AOh + (size_t)(m0 + row) * 256 + c * 8);
            cp16(Ws0 + row * 40 + c * 8, Wo16 + (size_t)(n0 + row) * 256 + c * 8);
        }
        CP_COMMIT();

        const int arow = wm + (lane & 7) + ((lane >> 3) & 1) * 8;
        const int acol = ((lane >> 4) << 3);
        const int brow = wn + ((lane >> 4) << 3) + (lane & 7);
        const int bcol = ((lane >> 3) & 1) << 3;

        for (int p = 0; p < 8; ++p) {
            CP_WAIT0();
            __syncthreads();
            if (p < 7) {
                int k0 = (p + 1) * 32, buf = (p + 1) & 1;
#pragma unroll
                for (int i = 0; i < 2; ++i) {
                    int idx = t + i * 128, row = idx >> 2, c = idx & 3;
                    cp16(Xs0 + buf * 2560 + row * 40 + c * 8,
                         AOh + (size_t)(m0 + row) * 256 + k0 + c * 8);
                    cp16(Ws0 + buf * 2560 + row * 40 + c * 8,
                         Wo16 + (size_t)(n0 + row) * 256 + k0 + c * 8);
                }
            }
            CP_COMMIT();

            const __half* Xb = Xs0 + (p & 1) * 2560;
            const __half* Wb = Ws0 + (p & 1) * 2560;
#pragma unroll
            for (int kc = 0; kc < 2; ++kc) {
                unsigned a[2][4], bb[4][2];
#pragma unroll
                for (int mt = 0; mt < 2; ++mt)
                    ldsm4(a[mt][0], a[mt][1], a[mt][2], a[mt][3],
                          Xb + (arow + mt * 16) * 40 + kc * 16 + acol);
#pragma unroll
                for (int np = 0; np < 2; ++np)
                    ldsm4(bb[np * 2][0], bb[np * 2][1], bb[np * 2 + 1][0], bb[np * 2 + 1][1],
                          Wb + (brow + np * 16) * 40 + kc * 16 + bcol);
#pragma unroll
                for (int mt = 0; mt < 2; ++mt)
#pragma unroll
                    for (int nt = 0; nt < 4; ++nt)
                        mma_f16(acc[mt][nt], a[mt][0], a[mt][1], a[mt][2], a[mt][3],
                                bb[nt][0], bb[nt][1]);
            }
        }

#pragma unroll
        for (int mt = 0; mt < 2; ++mt) {
#pragma unroll
            for (int nt = 0; nt < 4; ++nt) {
                int r = m0 + wm + mt * 16 + g;
                int c = n0 + wn + nt * 8 + 2 * l;
                *(float2*)(Cout + (size_t)r * 256 + c)       = make_float2(acc[mt][nt][0], acc[mt][nt][1]);
                *(float2*)(Cout + (size_t)(r + 8) * 256 + c) = make_float2(acc[mt][nt][2], acc[mt][nt][3]);
            }
        }
        return;
    }

    // ======================= attention block (v11 logic) =======================
    const int qt = blockIdx.x & 7;
    const int bh = blockIdx.x >> 3;
    const int b  = bh >> 3, hh = bh & 7;
    const int q0 = qt * 64;
    const size_t bN = (size_t)b * NSEQ;
    const int R0 = warp * 16 + g;
    const float we = We[hh] * 1.4426950408889634f;   // log2 domain

    __half* Ks0 = dsm;            // 2 x 64x40
    __half* Vs0 = dsm + 5120;     // 2 x 64x40
    __half* Es0 = dsm + 10240;    // 2 x 64x72

    const int arow = warp * 16 + (lane & 7) + ((lane >> 3) & 1) * 8;
    const int acol = ((lane >> 4) << 3);
    const int krow = (lane & 7);
    const int kcol = ((lane >> 3) << 3);

#pragma unroll
    for (int i = 0; i < 2; ++i) {
        int idx = t + i * 128;
        int row = idx >> 2, c = idx & 3;
        uint4 v = *(const uint4*)(Qh + ((bN + q0 + row) * DMODEL) + hh * HDIM + c * 8);
        *(uint4*)&Ks0[row * KLDH + c * 8] = v;
    }
    __syncthreads();

    unsigned qa[2][4];
    ldsm4(qa[0][0], qa[0][1], qa[0][2], qa[0][3], Ks0 + arow * KLDH + acol);
    ldsm4(qa[1][0], qa[1][1], qa[1][2], qa[1][3], Ks0 + arow * KLDH + 16 + acol);
    __syncthreads();

    float m0r = -1e30f, m1r = -1e30f, l0r = 0.f, l1r = 0.f;
    float o[4][4];
#pragma unroll
    for (int nt = 0; nt < 4; ++nt)
#pragma unroll
        for (int i = 0; i < 4; ++i) o[nt][i] = 0.f;

    const int kv_row = t >> 2, kv_c = t & 3;
    const int em_row = t >> 3, em_c = t & 7;

#pragma unroll
    for (int i = 0; i < 2; ++i) {
        int row = kv_row + i * 32;
        cp16(&Ks0[row * KLDH + kv_c * 8], Kh + (bN + row) * DMODEL + hh * HDIM + kv_c * 8);
        cp16(&Vs0[row * KLDH + kv_c * 8], Vh + (bN + row) * DMODEL + hh * HDIM + kv_c * 8);
    }
#pragma unroll
    for (int i = 0; i < 4; ++i) {
        int row = em_row + i * 16;
        cp16(&Es0[row * ELDH + em_c * 8], em + ((bN + q0 + row) * NSEQ) + em_c * 8);
    }
    CP_COMMIT();

    for (int it = 0; it < 8; ++it) {
        CP_WAIT0();
        __syncthreads();
        if (it < 7) {
            int jt = (it + 1) * 64, buf = (it + 1) & 1;
#pragma unroll
            for (int i = 0; i < 2; ++i) {
                int row = kv_row + i * 32;
                cp16(&Ks0[buf * 2560 + row * KLDH + kv_c * 8],
                     Kh + (bN + jt + row) * DMODEL + hh * HDIM + kv_c * 8);
                cp16(&Vs0[buf * 2560 + row * KLDH + kv_c * 8],
                     Vh + (bN + jt + row) * DMODEL + hh * HDIM + kv_c * 8);
            }
#pragma unroll
            for (int i = 0; i < 4; ++i) {
                int row = em_row + i * 16;
                cp16(&Es0[buf * 4608 + row * ELDH + em_c * 8],
                     em + ((bN + q0 + row) * NSEQ) + jt + em_c * 8);
            }
        }
        CP_COMMIT();

        const __half* Kb = Ks0 + (it & 1) * 2560;
        const __half* Eb = Es0 + (it & 1) * 4608;
        const __half* Vb = Vs0 + (it & 1) * 2560;

        float s[8][4];
#pragma unroll
        for (int nt = 0; nt < 8; ++nt) {
            s[nt][0] = s[nt][1] = s[nt][2] = s[nt][3] = 0.f;
            unsigned b0, b1, b2, b3;
            ldsm4(b0, b1, b2, b3, Kb + (8 * nt + krow) * KLDH + kcol);
            mma_f16(s[nt], qa[0][0], qa[0][1], qa[0][2], qa[0][3], b0, b1);
            mma_f16(s[nt], qa[1][0], qa[1][1], qa[1][2], qa[1][3], b2, b3);
        }

        float mn0 = m0r, mn1 = m1r;
#pragma unroll
        for (int i = 0; i < 4; ++i) {
            unsigned e0, e1, e2, e3;
            ldsm4(e0, e1, e2, e3, Eb + arow * ELDH + i * 16 + acol);
            float2 f0 = __half22float2(*(__half2*)&e0);
            float2 f1 = __half22float2(*(__half2*)&e1);
            float2 f2 = __half22float2(*(__half2*)&e2);
            float2 f3 = __half22float2(*(__half2*)&e3);
            int n0i = 2 * i, n1i = 2 * i + 1;
            s[n0i][0] = fmaxf(fmaf(we, f0.x, s[n0i][0]), -1e30f);
            s[n0i][1] = fmaxf(fmaf(we, f0.y, s[n0i][1]), -1e30f);
            s[n0i][2] = fmaxf(fmaf(we, f1.x, s[n0i][2]), -1e30f);
            s[n0i][3] = fmaxf(fmaf(we, f1.y, s[n0i][3]), -1e30f);
            s[n1i][0] = fmaxf(fmaf(we, f2.x, s[n1i][0]), -1e30f);
            s[n1i][1] = fmaxf(fmaf(we, f2.y, s[n1i][1]), -1e30f);
            s[n1i][2] = fmaxf(fmaf(we, f3.x, s[n1i][2]), -1e30f);
            s[n1i][3] = fmaxf(fmaf(we, f3.y, s[n1i][3]), -1e30f);
            mn0 = fmaxf(mn0, fmaxf(fmaxf(s[n0i][0], s[n0i][1]), fmaxf(s[n1i][0], s[n1i][1])));
            mn1 = fmaxf(mn1, fmaxf(fmaxf(s[n0i][2], s[n0i][3]), fmaxf(s[n1i][2], s[n1i][3])));
        }
        mn0 = fmaxf(mn0, __shfl_xor_sync(0xffffffff, mn0, 1));
        mn0 = fmaxf(mn0, __shfl_xor_sync(0xffffffff, mn0, 2));
        mn1 = fmaxf(mn1, __shfl_xor_sync(0xffffffff, mn1, 1));
        mn1 = fmaxf(mn1, __shfl_xor_sync(0xffffffff, mn1, 2));

        float corr0 = exp2f(m0r - mn0);
        float corr1 = exp2f(m1r - mn1);
        m0r = mn0; m1r = mn1;

        unsigned ph[8][2];
        float ps0 = 0.f, ps1 = 0.f;
#pragma unroll
        for (int nt = 0; nt < 8; ++nt) {
            __half2 x01 = __floats2half2_rn(s[nt][0] - mn0, s[nt][1] - mn0);
            __half2 x23 = __floats2half2_rn(s[nt][2] - mn1, s[nt][3] - mn1);
            __half2 p01 = h2exp2(x01);
            __half2 p23 = h2exp2(x23);
            ph[nt][0] = *(unsigned*)&p01;
            ph[nt][1] = *(unsigned*)&p23;
            float2 f01 = __half22float2(p01);
            float2 f23 = __half22float2(p23);
            ps0 += f01.x + f01.y;
            ps1 += f23.x + f23.y;
        }
        ps0 += __shfl_xor_sync(0xffffffff, ps0, 1);
        ps0 += __shfl_xor_sync(0xffffffff, ps0, 2);
        ps1 += __shfl_xor_sync(0xffffffff, ps1, 1);
        ps1 += __shfl_xor_sync(0xffffffff, ps1, 2);
        l0r = l0r * corr0 + ps0;
        l1r = l1r * corr1 + ps1;

#pragma unroll
        for (int nt = 0; nt < 4; ++nt) {
            o[nt][0] *= corr0; o[nt][1] *= corr0;
            o[nt][2] *= corr1; o[nt][3] *= corr1;
        }

        const int vkey = ((lane >> 3) & 1) << 3;
        const int vd   = ((lane >> 4) & 1) << 3;
        const int vr   = lane & 7;
#pragma unroll
        for (int kc = 0; kc < 4; ++kc) {
            unsigned a0 = ph[2 * kc][0];
            unsigned a1 = ph[2 * kc][1];
            unsigned a2 = ph[2 * kc + 1][0];
            unsigned a3 = ph[2 * kc + 1][1];
            unsigned v0, v1, v2, v3, v4, v5, v6, v7;
            const __half* basep = Vb + (16 * kc + vkey + vr) * KLDH + vd;
            ldsm4t(v0, v1, v2, v3, basep);
            ldsm4t(v4, v5, v6, v7, basep + 16);
            mma_f16(o[0], a0, a1, a2, a3, v0, v1);
            mma_f16(o[1], a0, a1, a2, a3, v2, v3);
            mma_f16(o[2], a0, a1, a2, a3, v4, v5);
            mma_f16(o[3], a0, a1, a2, a3, v6, v7);
        }
    }

    const float inv0 = 1.0f / l0r;
    const float inv1 = 1.0f / l1r;
#pragma unroll
    for (int nt = 0; nt < 4; ++nt) {
        int c = hh * HDIM + nt * 8 + 2 * l;
        *(__half2*)(AOh + (bN + q0 + R0) * DMODEL + c) =
            __floats2half2_rn(o[nt][0] * inv0, o[nt][1] * inv0);
        *(__half2*)(AOh + (bN + q0 + R0 + 8) * DMODEL + c) =
            __floats2half2_rn(o[nt][2] * inv1, o[nt][3] * inv1);
    }

    // signal: rows [b*512 + q0, +64) of AO complete for this head
    __syncthreads();
    if (t == 0) {
        __threadfence();
        atomicAdd(&g_done[b * 8 + qt], 1);
    }
}

// ----------------------------------------------------------------------------
// launch
// ----------------------------------------------------------------------------
extern "C" void kernel_launch(void* const* d_in, const int* in_sizes, int n_in,
                              void* d_out, int out_size)
{
    const float* h    = (const float*)d_in[0];
    const float* edge = (const float*)d_in[1];
    const int*   mask = (const int*)  d_in[2];
    const float* Wq   = (const float*)d_in[3];
    const float* Wk   = (const float*)d_in[4];
    const float* Wv   = (const float*)d_in[5];
    const float* We   = (const float*)d_in[6];
    const float* Wo   = (const float*)d_in[7];
    float* out = (float*)d_out;

    __half *h16, *q16, *k16, *v16, *ao16, *emh, *w16;
    cudaGetSymbolAddress((void**)&h16,  g_h16);
    cudaGetSymbolAddress((void**)&q16,  g_q16);
    cudaGetSymbolAddress((void**)&k16,  g_k16);
    cudaGetSymbolAddress((void**)&v16,  g_v16);
    cudaGetSymbolAddress((void**)&ao16, g_ao16);
    cudaGetSymbolAddress((void**)&emh,  g_em);
    cudaGetSymbolAddress((void**)&w16,  g_w16);

    cudaFuncSetAttribute(gemm_qkv, cudaFuncAttributeMaxDynamicSharedMemorySize, GEMM_SMEM_BYTES);

    prep_hw<<<(N_HW8 + 255) / 256, 256>>>(h, Wq, Wk, Wv, Wo, h16, w16);

    // by<32: em-prep streaming blocks (first); by>=32: 128x128 gemm tiles
    gemm_qkv<<<dim3(6, 160), 256, GEMM_SMEM_BYTES>>>(h16, w16, q16, k16, v16, edge, mask, emh);

    // 2048 attention blocks + 1024 flag-gated output-GEMM tiles
    attn_out<<<ATTN_BLOCKS + OUT_BLOCKS, 128, ATTN_SMEM_BYTES>>>(
        q16, k16, v16, emh, We, ao16, w16 + 3 * DMODEL * DMODEL, out);
}

// round 14
// speedup vs baseline: 1.0234x; 1.0041x over previous
#include <cuda_runtime.h>
#include <cuda_fp16.h>
#include <math.h>

// ----------------------------------------------------------------------------
// EdgeBiasedAttention — v14: v11 (best: 114.7us) + prep_hw MLP=4.
// B=32, N=512, D=256, H=8, HD=32
// ----------------------------------------------------------------------------

#define BATCH 32
#define NSEQ  512
#define DMODEL 256
#define NHEAD 8
#define HDIM  32
#define MROWS (BATCH * NSEQ)  // 16384

#define N_H8 (MROWS * DMODEL / 8)          // 524288
#define N_W8 (DMODEL * DMODEL / 8)         // 8192
#define N_E8 (BATCH * NSEQ * NSEQ / 8)     // 1048576
#define N_HW8 (N_H8 + 4 * N_W8)            // 557056

// fp16 scratch
__device__ __half g_h16 [MROWS * DMODEL];
__device__ __half g_q16 [MROWS * DMODEL];
__device__ __half g_k16 [MROWS * DMODEL];
__device__ __half g_v16 [MROWS * DMODEL];
__device__ __half g_ao16[MROWS * DMODEL];
__device__ __half g_em  [BATCH * NSEQ * NSEQ];   // masked edge (NaN = masked)
__device__ __half g_w16 [4 * DMODEL * DMODEL];   // Wq, Wk, Wv, Wo fp16

// ---------------- helpers ----------------
__device__ __forceinline__ void mma_f16(float c[4],
                                        unsigned a0, unsigned a1, unsigned a2, unsigned a3,
                                        unsigned b0, unsigned b1)
{
    asm volatile(
        "mma.sync.aligned.m16n8k16.row.col.f32.f16.f16.f32 "
        "{%0,%1,%2,%3}, {%4,%5,%6,%7}, {%8,%9}, {%0,%1,%2,%3};"
        : "+f"(c[0]), "+f"(c[1]), "+f"(c[2]), "+f"(c[3])
        : "r"(a0), "r"(a1), "r"(a2), "r"(a3), "r"(b0), "r"(b1));
}

__device__ __forceinline__ void cp16(void* sdst, const void* gsrc) {
    unsigned s = (unsigned)__cvta_generic_to_shared(sdst);
    asm volatile("cp.async.cg.shared.global [%0], [%1], 16;" :: "r"(s), "l"(gsrc));
}
#define CP_COMMIT() asm volatile("cp.async.commit_group;")
#define CP_WAIT0()  asm volatile("cp.async.wait_group 0;" ::: "memory")
#define CP_WAIT2()  asm volatile("cp.async.wait_group 2;" ::: "memory")

__device__ __forceinline__ void ldsm4(unsigned& r0, unsigned& r1, unsigned& r2, unsigned& r3,
                                      const __half* p)
{
    unsigned s = (unsigned)__cvta_generic_to_shared(p);
    asm volatile("ldmatrix.sync.aligned.m8n8.x4.shared.b16 {%0,%1,%2,%3}, [%4];"
                 : "=r"(r0), "=r"(r1), "=r"(r2), "=r"(r3) : "r"(s));
}
__device__ __forceinline__ void ldsm4t(unsigned& r0, unsigned& r1, unsigned& r2, unsigned& r3,
                                       const __half* p)
{
    unsigned s = (unsigned)__cvta_generic_to_shared(p);
    asm volatile("ldmatrix.sync.aligned.m8n8.x4.trans.shared.b16 {%0,%1,%2,%3}, [%4];"
                 : "=r"(r0), "=r"(r1), "=r"(r2), "=r"(r3) : "r"(s));
}

__device__ __forceinline__ uint4 pack8(float4 a, float4 b) {
    uint4 o;
    __half2 h0 = __floats2half2_rn(a.x, a.y);
    __half2 h1 = __floats2half2_rn(a.z, a.w);
    __half2 h2 = __floats2half2_rn(b.x, b.y);
    __half2 h3 = __floats2half2_rn(b.z, b.w);
    o.x = *(unsigned*)&h0; o.y = *(unsigned*)&h1;
    o.z = *(unsigned*)&h2; o.w = *(unsigned*)&h3;
    return o;
}

// ---------------- preprocessing: h + weights, 2 uint4 outputs/thread --------
__global__ __launch_bounds__(256) void prep_hw(
    const float* __restrict__ h,
    const float* __restrict__ Wq, const float* __restrict__ Wk,
    const float* __restrict__ Wv, const float* __restrict__ Wo,
    __half* __restrict__ h16, __half* __restrict__ w16)
{
    int i0 = (blockIdx.x * 256 + threadIdx.x) * 2;
#pragma unroll
    for (int k = 0; k < 2; ++k) {
        int i = i0 + k;
        if (i < N_H8) {
            const float4* s = (const float4*)h + (size_t)i * 2;
            ((uint4*)h16)[i] = pack8(s[0], s[1]);
        } else if (i < N_HW8) {
            int j = i - N_H8;
            int which = j >> 13, off = j & (N_W8 - 1);
            const float* W = which == 0 ? Wq : which == 1 ? Wk : which == 2 ? Wv : Wo;
            const float4* s = (const float4*)W + (size_t)off * 2;
            ((uint4*)w16)[(size_t)which * N_W8 + off] = pack8(s[0], s[1]);
        }
    }
}

// ----------------------------------------------------------------------------
// GEMM core: 128x128 tile, BK=32, 4-stage cp.async pipeline (v11).
// Dynamic smem: Xs[4][128*40], Ws[4][128*40]  (81920 B)
// ----------------------------------------------------------------------------
#define GSTG (128 * 40)
#define GEMM_SMEM_BYTES (8 * GSTG * 2)

#define GEMM_BODY(X, W, ACC)                                                         \
    __half* Xs = gsm;                                                                \
    __half* Ws = gsm + 4 * GSTG;                                                     \
    const int srow = t >> 2, sc = t & 3;                                             \
    _Pragma("unroll")                                                                \
    for (int st = 0; st < 3; ++st) {                                                 \
        int k0 = st * 32;                                                            \
        _Pragma("unroll")                                                            \
        for (int i = 0; i < 2; ++i) {                                                \
            int row = srow + i * 64;                                                 \
            cp16(Xs + st * GSTG + row * 40 + sc * 8, X + (size_t)(m0 + row) * 256 + k0 + sc * 8); \
            cp16(Ws + st * GSTG + row * 40 + sc * 8, W + (size_t)(n0 + row) * 256 + k0 + sc * 8); \
        }                                                                            \
        CP_COMMIT();                                                                 \
    }                                                                                \
    const int arow = wm + (lane & 7) + ((lane >> 3) & 1) * 8;                        \
    const int acol = ((lane >> 4) << 3);                                             \
    const int brow = wn + ((lane >> 4) << 3) + (lane & 7);                           \
    const int bcol = ((lane >> 3) & 1) << 3;                                         \
    for (int p = 0; p < 8; ++p) {                                                    \
        CP_WAIT2();                                                                  \
        __syncthreads();                                                             \
        if (p < 5) {                                                                 \
            int k0 = (p + 3) * 32, buf = (p + 3) & 3;                                \
            _Pragma("unroll")                                                        \
            for (int i = 0; i < 2; ++i) {                                            \
                int row = srow + i * 64;                                             \
                cp16(Xs + buf * GSTG + row * 40 + sc * 8, X + (size_t)(m0 + row) * 256 + k0 + sc * 8); \
                cp16(Ws + buf * GSTG + row * 40 + sc * 8, W + (size_t)(n0 + row) * 256 + k0 + sc * 8); \
            }                                                                        \
        }                                                                            \
        CP_COMMIT();                                                                 \
        const __half* Xb = Xs + (p & 3) * GSTG;                                      \
        const __half* Wb = Ws + (p & 3) * GSTG;                                      \
        _Pragma("unroll")                                                            \
        for (int kc = 0; kc < 2; ++kc) {                                             \
            unsigned a[4][4], bb[4][2];                                              \
            _Pragma("unroll")                                                        \
            for (int mt = 0; mt < 4; ++mt)                                           \
                ldsm4(a[mt][0], a[mt][1], a[mt][2], a[mt][3],                        \
                      Xb + (arow + mt * 16) * 40 + kc * 16 + acol);                  \
            _Pragma("unroll")                                                        \
            for (int np = 0; np < 2; ++np)                                           \
                ldsm4(bb[np * 2][0], bb[np * 2][1], bb[np * 2 + 1][0], bb[np * 2 + 1][1], \
                      Wb + (brow + np * 16) * 40 + kc * 16 + bcol);                  \
            _Pragma("unroll")                                                        \
            for (int mt = 0; mt < 4; ++mt)                                           \
                _Pragma("unroll")                                                    \
                for (int nt = 0; nt < 4; ++nt)                                       \
                    mma_f16(ACC[mt][nt], a[mt][0], a[mt][1], a[mt][2], a[mt][3],     \
                            bb[nt][0], bb[nt][1]);                                   \
        }                                                                            \
    }

// Fused QKV GEMM + em preprocessing. grid (6, 160):
// by<32: em-prep streaming blocks (first); by>=32: 128x128 gemm tiles.
__global__ __launch_bounds__(256, 2) void gemm_qkv(
    const __half* __restrict__ X, const __half* __restrict__ Wcat,
    __half* __restrict__ Qd, __half* __restrict__ Kd, __half* __restrict__ Vd,
    const float* __restrict__ edge, const int* __restrict__ mask,
    __half* __restrict__ em)
{
    extern __shared__ __half gsm[];
    const int t = threadIdx.x;

    if (blockIdx.y < 32) {
        const float QNAN = __int_as_float(0x7fc00000);
        int chunk = blockIdx.y * 6 + blockIdx.x;             // 0..191
        for (int j = chunk * 256 + t; j < N_E8; j += 192 * 256) {
            const float4* es = (const float4*)edge + (size_t)j * 2;
            const int4*   ms = (const int4*)mask + (size_t)j * 2;
            float4 e0 = es[0], e1 = es[1];
            int4   m0v = ms[0], m1v = ms[1];
            float4 f0 = make_float4(m0v.x ? e0.x : QNAN, m0v.y ? e0.y : QNAN,
                                    m0v.z ? e0.z : QNAN, m0v.w ? e0.w : QNAN);
            float4 f1 = make_float4(m1v.x ? e1.x : QNAN, m1v.y ? e1.y : QNAN,
                                    m1v.z ? e1.z : QNAN, m1v.w ? e1.w : QNAN);
            ((uint4*)em)[j] = pack8(f0, f1);
        }
        return;
    }

    const int warp = t >> 5, lane = t & 31;
    const int g = lane >> 2, l = lane & 3;
    const int m0 = (blockIdx.y - 32) * 128, n0 = blockIdx.x * 128;
    const int wm = (warp >> 2) * 64, wn = (warp & 3) * 32;
    const int which = blockIdx.x >> 1;
    __half* dst = which == 0 ? Qd : which == 1 ? Kd : Vd;
    const int nloc = n0 & 255;
    const float oscale = (which == 0) ? 0.17677669529663687f * 1.4426950408889634f : 1.0f;

    float acc[4][4][4];
#pragma unroll
    for (int mt = 0; mt < 4; ++mt)
#pragma unroll
        for (int nt = 0; nt < 4; ++nt)
#pragma unroll
            for (int i = 0; i < 4; ++i) acc[mt][nt][i] = 0.f;

    GEMM_BODY(X, Wcat, acc)

#pragma unroll
    for (int mt = 0; mt < 4; ++mt) {
#pragma unroll
        for (int nt = 0; nt < 4; ++nt) {
            int r = m0 + wm + mt * 16 + g;
            int c = nloc + wn + nt * 8 + 2 * l;
            *(__half2*)(dst + (size_t)r * 256 + c) =
                __floats2half2_rn(acc[mt][nt][0] * oscale, acc[mt][nt][1] * oscale);
            *(__half2*)(dst + (size_t)(r + 8) * 256 + c) =
                __floats2half2_rn(acc[mt][nt][2] * oscale, acc[mt][nt][3] * oscale);
        }
    }
}

// Output GEMM: fp32 out, 128x128 tiles, grid (2, 128)
__global__ __launch_bounds__(256, 2) void gemm_out(const __half* __restrict__ X,
                                                   const __half* __restrict__ W,
                                                   float* __restrict__ C)
{
    extern __shared__ __half gsm[];

    const int t = threadIdx.x, warp = t >> 5, lane = t & 31;
    const int g = lane >> 2, l = lane & 3;
    const int m0 = blockIdx.y * 128, n0 = blockIdx.x * 128;
    const int wm = (warp >> 2) * 64, wn = (warp & 3) * 32;

    float acc[4][4][4];
#pragma unroll
    for (int mt = 0; mt < 4; ++mt)
#pragma unroll
        for (int nt = 0; nt < 4; ++nt)
#pragma unroll
            for (int i = 0; i < 4; ++i) acc[mt][nt][i] = 0.f;

    GEMM_BODY(X, W, acc)

#pragma unroll
    for (int mt = 0; mt < 4; ++mt) {
#pragma unroll
        for (int nt = 0; nt < 4; ++nt) {
            int r = m0 + wm + mt * 16 + g;
            int c = n0 + wn + nt * 8 + 2 * l;
            *(float2*)(C + (size_t)r * 256 + c)       = make_float2(acc[mt][nt][0], acc[mt][nt][1]);
            *(float2*)(C + (size_t)(r + 8) * 256 + c) = make_float2(acc[mt][nt][2], acc[mt][nt][3]);
        }
    }
}

// ----------------------------------------------------------------------------
// Attention (fp16) — v11 (occ 5 blocks/SM).
// ----------------------------------------------------------------------------
#define KLDH 40   // K/V row stride halves (80B) -> conflict-free
#define ELDH 72   // em row stride halves (144B) -> conflict-free

__global__ __launch_bounds__(128, 5) void attn_f16(
    const __half* __restrict__ Qh, const __half* __restrict__ Kh,
    const __half* __restrict__ Vh, const __half* __restrict__ em,
    const float* __restrict__ We, __half* __restrict__ AOh)
{
    __shared__ __half Ks[2][64 * KLDH];
    __shared__ __half Vs[2][64 * KLDH];
    __shared__ __half Es[2][64 * ELDH];

    const int t = threadIdx.x, warp = t >> 5, lane = t & 31;
    const int g = lane >> 2, l = lane & 3;
    const int bh = blockIdx.y;
    const int b  = bh >> 3, hh = bh & 7;
    const int q0 = blockIdx.x * 64;
    const size_t bN = (size_t)b * NSEQ;
    const int R0 = warp * 16 + g;
    const float we = We[hh] * 1.4426950408889634f;   // log2 domain

    const int arow = warp * 16 + (lane & 7) + ((lane >> 3) & 1) * 8;
    const int acol = ((lane >> 4) << 3);
    const int krow = (lane & 7);
    const int kcol = ((lane >> 3) << 3);

#pragma unroll
    for (int i = 0; i < 2; ++i) {
        int idx = t + i * 128;
        int row = idx >> 2, c = idx & 3;
        uint4 v = *(const uint4*)(Qh + ((bN + q0 + row) * DMODEL) + hh * HDIM + c * 8);
        *(uint4*)&Ks[0][row * KLDH + c * 8] = v;
    }
    __syncthreads();

    unsigned qa[2][4];
    ldsm4(qa[0][0], qa[0][1], qa[0][2], qa[0][3], Ks[0] + arow * KLDH + acol);
    ldsm4(qa[1][0], qa[1][1], qa[1][2], qa[1][3], Ks[0] + arow * KLDH + 16 + acol);
    __syncthreads();

    float m0r = -1e30f, m1r = -1e30f, l0r = 0.f, l1r = 0.f;
    float o[4][4];
#pragma unroll
    for (int nt = 0; nt < 4; ++nt)
#pragma unroll
        for (int i = 0; i < 4; ++i) o[nt][i] = 0.f;

    const int kv_row = t >> 2, kv_c = t & 3;
    const int em_row = t >> 3, em_c = t & 7;

#pragma unroll
    for (int i = 0; i < 2; ++i) {
        int row = kv_row + i * 32;
        cp16(&Ks[0][row * KLDH + kv_c * 8], Kh + (bN + row) * DMODEL + hh * HDIM + kv_c * 8);
        cp16(&Vs[0][row * KLDH + kv_c * 8], Vh + (bN + row) * DMODEL + hh * HDIM + kv_c * 8);
    }
#pragma unroll
    for (int i = 0; i < 4; ++i) {
        int row = em_row + i * 16;
        cp16(&Es[0][row * ELDH + em_c * 8], em + ((bN + q0 + row) * NSEQ) + em_c * 8);
    }
    CP_COMMIT();

    for (int it = 0; it < 8; ++it) {
        CP_WAIT0();
        __syncthreads();
        if (it < 7) {
            int jt = (it + 1) * 64, buf = (it + 1) & 1;
#pragma unroll
            for (int i = 0; i < 2; ++i) {
                int row = kv_row + i * 32;
                cp16(&Ks[buf][row * KLDH + kv_c * 8],
                     Kh + (bN + jt + row) * DMODEL + hh * HDIM + kv_c * 8);
                cp16(&Vs[buf][row * KLDH + kv_c * 8],
                     Vh + (bN + jt + row) * DMODEL + hh * HDIM + kv_c * 8);
            }
#pragma unroll
            for (int i = 0; i < 4; ++i) {
                int row = em_row + i * 16;
                cp16(&Es[buf][row * ELDH + em_c * 8],
                     em + ((bN + q0 + row) * NSEQ) + jt + em_c * 8);
            }
        }
        CP_COMMIT();

        const __half* Kb = Ks[it & 1];
        const __half* Eb = Es[it & 1];
        const __half* Vb = Vs[it & 1];

        float s[8][4];
#pragma unroll
        for (int nt = 0; nt < 8; ++nt) {
            s[nt][0] = s[nt][1] = s[nt][2] = s[nt][3] = 0.f;
            unsigned b0, b1, b2, b3;
            ldsm4(b0, b1, b2, b3, Kb + (8 * nt + krow) * KLDH + kcol);
            mma_f16(s[nt], qa[0][0], qa[0][1], qa[0][2], qa[0][3], b0, b1);
            mma_f16(s[nt], qa[1][0], qa[1][1], qa[1][2], qa[1][3], b2, b3);
        }

        float mn0 = m0r, mn1 = m1r;
#pragma unroll
        for (int i = 0; i < 4; ++i) {
            unsigned e0, e1, e2, e3;
            ldsm4(e0, e1, e2, e3, Eb + arow * ELDH + i * 16 + acol);
            float2 f0 = __half22float2(*(__half2*)&e0);
            float2 f1 = __half22float2(*(__half2*)&e1);
            float2 f2 = __half22float2(*(__half2*)&e2);
            float2 f3 = __half22float2(*(__half2*)&e3);
            int n0i = 2 * i, n1i = 2 * i + 1;
            s[n0i][0] = fmaxf(fmaf(we, f0.x, s[n0i][0]), -1e30f);
            s[n0i][1] = fmaxf(fmaf(we, f0.y, s[n0i][1]), -1e30f);
            s[n0i][2] = fmaxf(fmaf(we, f1.x, s[n0i][2]), -1e30f);
            s[n0i][3] = fmaxf(fmaf(we, f1.y, s[n0i][3]), -1e30f);
            s[n1i][0] = fmaxf(fmaf(we, f2.x, s[n1i][0]), -1e30f);
            s[n1i][1] = fmaxf(fmaf(we, f2.y, s[n1i][1]), -1e30f);
            s[n1i][2] = fmaxf(fmaf(we, f3.x, s[n1i][2]), -1e30f);
            s[n1i][3] = fmaxf(fmaf(we, f3.y, s[n1i][3]), -1e30f);
            mn0 = fmaxf(mn0, fmaxf(fmaxf(s[n0i][0], s[n0i][1]), fmaxf(s[n1i][0], s[n1i][1])));
            mn1 = fmaxf(mn1, fmaxf(fmaxf(s[n0i][2], s[n0i][3]), fmaxf(s[n1i][2], s[n1i][3])));
        }
        mn0 = fmaxf(mn0, __shfl_xor_sync(0xffffffff, mn0, 1));
        mn0 = fmaxf(mn0, __shfl_xor_sync(0xffffffff, mn0, 2));
        mn1 = fmaxf(mn1, __shfl_xor_sync(0xffffffff, mn1, 1));
        mn1 = fmaxf(mn1, __shfl_xor_sync(0xffffffff, mn1, 2));

        float corr0 = exp2f(m0r - mn0);
        float corr1 = exp2f(m1r - mn1);
        m0r = mn0; m1r = mn1;

        unsigned ph[8][2];
        float ps0 = 0.f, ps1 = 0.f;
#pragma unroll
        for (int nt = 0; nt < 8; ++nt) {
            __half2 x01 = __floats2half2_rn(s[nt][0] - mn0, s[nt][1] - mn0);
            __half2 x23 = __floats2half2_rn(s[nt][2] - mn1, s[nt][3] - mn1);
            __half2 p01 = h2exp2(x01);
            __half2 p23 = h2exp2(x23);
            ph[nt][0] = *(unsigned*)&p01;
            ph[nt][1] = *(unsigned*)&p23;
            float2 f01 = __half22float2(p01);
            float2 f23 = __half22float2(p23);
            ps0 += f01.x + f01.y;
            ps1 += f23.x + f23.y;
        }
        ps0 += __shfl_xor_sync(0xffffffff, ps0, 1);
        ps0 += __shfl_xor_sync(0xffffffff, ps0, 2);
        ps1 += __shfl_xor_sync(0xffffffff, ps1, 1);
        ps1 += __shfl_xor_sync(0xffffffff, ps1, 2);
        l0r = l0r * corr0 + ps0;
        l1r = l1r * corr1 + ps1;

#pragma unroll
        for (int nt = 0; nt < 4; ++nt) {
            o[nt][0] *= corr0; o[nt][1] *= corr0;
            o[nt][2] *= corr1; o[nt][3] *= corr1;
        }

        const int vkey = ((lane >> 3) & 1) << 3;
        const int vd   = ((lane >> 4) & 1) << 3;
        const int vr   = lane & 7;
#pragma unroll
        for (int kc = 0; kc < 4; ++kc) {
            unsigned a0 = ph[2 * kc][0];
            unsigned a1 = ph[2 * kc][1];
            unsigned a2 = ph[2 * kc + 1][0];
            unsigned a3 = ph[2 * kc + 1][1];
            unsigned v0, v1, v2, v3, v4, v5, v6, v7;
            const __half* basep = Vb + (16 * kc + vkey + vr) * KLDH + vd;
            ldsm4t(v0, v1, v2, v3, basep);
            ldsm4t(v4, v5, v6, v7, basep + 16);
            mma_f16(o[0], a0, a1, a2, a3, v0, v1);
            mma_f16(o[1], a0, a1, a2, a3, v2, v3);
            mma_f16(o[2], a0, a1, a2, a3, v4, v5);
            mma_f16(o[3], a0, a1, a2, a3, v6, v7);
        }
    }

    const float inv0 = 1.0f / l0r;
    const float inv1 = 1.0f / l1r;
#pragma unroll
    for (int nt = 0; nt < 4; ++nt) {
        int c = hh * HDIM + nt * 8 + 2 * l;
        *(__half2*)(AOh + (bN + q0 + R0) * DMODEL + c) =
            __floats2half2_rn(o[nt][0] * inv0, o[nt][1] * inv0);
        *(__half2*)(AOh + (bN + q0 + R0 + 8) * DMODEL + c) =
            __floats2half2_rn(o[nt][2] * inv1, o[nt][3] * inv1);
    }
}

// ----------------------------------------------------------------------------
// launch
// ----------------------------------------------------------------------------
extern "C" void kernel_launch(void* const* d_in, const int* in_sizes, int n_in,
                              void* d_out, int out_size)
{
    const float* h    = (const float*)d_in[0];
    const float* edge = (const float*)d_in[1];
    const int*   mask = (const int*)  d_in[2];
    const float* Wq   = (const float*)d_in[3];
    const float* Wk   = (const float*)d_in[4];
    const float* Wv   = (const float*)d_in[5];
    const float* We   = (const float*)d_in[6];
    const float* Wo   = (const float*)d_in[7];
    float* out = (float*)d_out;

    __half *h16, *q16, *k16, *v16, *ao16, *emh, *w16;
    cudaGetSymbolAddress((void**)&h16,  g_h16);
    cudaGetSymbolAddress((void**)&q16,  g_q16);
    cudaGetSymbolAddress((void**)&k16,  g_k16);
    cudaGetSymbolAddress((void**)&v16,  g_v16);
    cudaGetSymbolAddress((void**)&ao16, g_ao16);
    cudaGetSymbolAddress((void**)&emh,  g_em);
    cudaGetSymbolAddress((void**)&w16,  g_w16);

    cudaFuncSetAttribute(gemm_qkv, cudaFuncAttributeMaxDynamicSharedMemorySize, GEMM_SMEM_BYTES);
    cudaFuncSetAttribute(gemm_out, cudaFuncAttributeMaxDynamicSharedMemorySize, GEMM_SMEM_BYTES);

    prep_hw<<<(N_HW8 / 2 + 255) / 256, 256>>>(h, Wq, Wk, Wv, Wo, h16, w16);

    // by<32: em-prep streaming blocks (first); by>=32: 128x128 gemm tiles
    gemm_qkv<<<dim3(6, 160), 256, GEMM_SMEM_BYTES>>>(h16, w16, q16, k16, v16, edge, mask, emh);

    attn_f16<<<dim3(NSEQ / 64, BATCH * NHEAD), 128>>>(q16, k16, v16, emh, We, ao16);

    gemm_out<<<dim3(2, MROWS / 128), 256, GEMM_SMEM_BYTES>>>(ao16, w16 + 3 * DMODEL * DMODEL, out);
}

// round 16
// speedup vs baseline: 1.0377x; 1.0140x over previous
#include <cuda_runtime.h>
#include <cuda_fp16.h>
#include <math.h>

// ----------------------------------------------------------------------------
// EdgeBiasedAttention — v15 (resubmit; R15 bench was an infra failure):
// v11 GEMMs/prep + attention retiled to 32 q-rows per warp
// (block = 128 queries, 2x ILP per warp, halved K/V overhead/query).
// B=32, N=512, D=256, H=8, HD=32
// ----------------------------------------------------------------------------

#define BATCH 32
#define NSEQ  512
#define DMODEL 256
#define NHEAD 8
#define HDIM  32
#define MROWS (BATCH * NSEQ)  // 16384

#define N_H8 (MROWS * DMODEL / 8)          // 524288
#define N_W8 (DMODEL * DMODEL / 8)         // 8192
#define N_E8 (BATCH * NSEQ * NSEQ / 8)     // 1048576
#define N_HW8 (N_H8 + 4 * N_W8)            // 557056

// fp16 scratch
__device__ __half g_h16 [MROWS * DMODEL];
__device__ __half g_q16 [MROWS * DMODEL];
__device__ __half g_k16 [MROWS * DMODEL];
__device__ __half g_v16 [MROWS * DMODEL];
__device__ __half g_ao16[MROWS * DMODEL];
__device__ __half g_em  [BATCH * NSEQ * NSEQ];   // masked edge (NaN = masked)
__device__ __half g_w16 [4 * DMODEL * DMODEL];   // Wq, Wk, Wv, Wo fp16

// ---------------- helpers ----------------
__device__ __forceinline__ void mma_f16(float c[4],
                                        unsigned a0, unsigned a1, unsigned a2, unsigned a3,
                                        unsigned b0, unsigned b1)
{
    asm volatile(
        "mma.sync.aligned.m16n8k16.row.col.f32.f16.f16.f32 "
        "{%0,%1,%2,%3}, {%4,%5,%6,%7}, {%8,%9}, {%0,%1,%2,%3};"
        : "+f"(c[0]), "+f"(c[1]), "+f"(c[2]), "+f"(c[3])
        : "r"(a0), "r"(a1), "r"(a2), "r"(a3), "r"(b0), "r"(b1));
}

__device__ __forceinline__ void cp16(void* sdst, const void* gsrc) {
    unsigned s = (unsigned)__cvta_generic_to_shared(sdst);
    asm volatile("cp.async.cg.shared.global [%0], [%1], 16;" :: "r"(s), "l"(gsrc));
}
#define CP_COMMIT() asm volatile("cp.async.commit_group;")
#define CP_WAIT0()  asm volatile("cp.async.wait_group 0;" ::: "memory")
#define CP_WAIT2()  asm volatile("cp.async.wait_group 2;" ::: "memory")

__device__ __forceinline__ void ldsm4(unsigned& r0, unsigned& r1, unsigned& r2, unsigned& r3,
                                      const __half* p)
{
    unsigned s = (unsigned)__cvta_generic_to_shared(p);
    asm volatile("ldmatrix.sync.aligned.m8n8.x4.shared.b16 {%0,%1,%2,%3}, [%4];"
                 : "=r"(r0), "=r"(r1), "=r"(r2), "=r"(r3) : "r"(s));
}
__device__ __forceinline__ void ldsm4t(unsigned& r0, unsigned& r1, unsigned& r2, unsigned& r3,
                                       const __half* p)
{
    unsigned s = (unsigned)__cvta_generic_to_shared(p);
    asm volatile("ldmatrix.sync.aligned.m8n8.x4.trans.shared.b16 {%0,%1,%2,%3}, [%4];"
                 : "=r"(r0), "=r"(r1), "=r"(r2), "=r"(r3) : "r"(s));
}

__device__ __forceinline__ uint4 pack8(float4 a, float4 b) {
    uint4 o;
    __half2 h0 = __floats2half2_rn(a.x, a.y);
    __half2 h1 = __floats2half2_rn(a.z, a.w);
    __half2 h2 = __floats2half2_rn(b.x, b.y);
    __half2 h3 = __floats2half2_rn(b.z, b.w);
    o.x = *(unsigned*)&h0; o.y = *(unsigned*)&h1;
    o.z = *(unsigned*)&h2; o.w = *(unsigned*)&h3;
    return o;
}

// ---------------- preprocessing: h + weights (v11 exact) ----------------
__global__ __launch_bounds__(256) void prep_hw(
    const float* __restrict__ h,
    const float* __restrict__ Wq, const float* __restrict__ Wk,
    const float* __restrict__ Wv, const float* __restrict__ Wo,
    __half* __restrict__ h16, __half* __restrict__ w16)
{
    int i = blockIdx.x * 256 + threadIdx.x;
    if (i < N_H8) {
        const float4* s = (const float4*)h + (size_t)i * 2;
        ((uint4*)h16)[i] = pack8(s[0], s[1]);
    } else if (i < N_HW8) {
        int j = i - N_H8;
        int which = j >> 13, off = j & (N_W8 - 1);
        const float* W = which == 0 ? Wq : which == 1 ? Wk : which == 2 ? Wv : Wo;
        const float4* s = (const float4*)W + (size_t)off * 2;
        ((uint4*)w16)[(size_t)which * N_W8 + off] = pack8(s[0], s[1]);
    }
}

// ----------------------------------------------------------------------------
// GEMM core: 128x128 tile, BK=32, 4-stage cp.async pipeline (v11).
// ----------------------------------------------------------------------------
#define GSTG (128 * 40)
#define GEMM_SMEM_BYTES (8 * GSTG * 2)

#define GEMM_BODY(X, W, ACC)                                                         \
    __half* Xs = gsm;                                                                \
    __half* Ws = gsm + 4 * GSTG;                                                     \
    const int srow = t >> 2, sc = t & 3;                                             \
    _Pragma("unroll")                                                                \
    for (int st = 0; st < 3; ++st) {                                                 \
        int k0 = st * 32;                                                            \
        _Pragma("unroll")                                                            \
        for (int i = 0; i < 2; ++i) {                                                \
            int row = srow + i * 64;                                                 \
            cp16(Xs + st * GSTG + row * 40 + sc * 8, X + (size_t)(m0 + row) * 256 + k0 + sc * 8); \
            cp16(Ws + st * GSTG + row * 40 + sc * 8, W + (size_t)(n0 + row) * 256 + k0 + sc * 8); \
        }                                                                            \
        CP_COMMIT();                                                                 \
    }                                                                                \
    const int arow = wm + (lane & 7) + ((lane >> 3) & 1) * 8;                        \
    const int acol = ((lane >> 4) << 3);                                             \
    const int brow = wn + ((lane >> 4) << 3) + (lane & 7);                           \
    const int bcol = ((lane >> 3) & 1) << 3;                                         \
    for (int p = 0; p < 8; ++p) {                                                    \
        CP_WAIT2();                                                                  \
        __syncthreads();                                                             \
        if (p < 5) {                                                                 \
            int k0 = (p + 3) * 32, buf = (p + 3) & 3;                                \
            _Pragma("unroll")                                                        \
            for (int i = 0; i < 2; ++i) {                                            \
                int row = srow + i * 64;                                             \
                cp16(Xs + buf * GSTG + row * 40 + sc * 8, X + (size_t)(m0 + row) * 256 + k0 + sc * 8); \
                cp16(Ws + buf * GSTG + row * 40 + sc * 8, W + (size_t)(n0 + row) * 256 + k0 + sc * 8); \
            }                                                                        \
        }                                                                            \
        CP_COMMIT();                                                                 \
        const __half* Xb = Xs + (p & 3) * GSTG;                                      \
        const __half* Wb = Ws + (p & 3) * GSTG;                                      \
        _Pragma("unroll")                                                            \
        for (int kc = 0; kc < 2; ++kc) {                                             \
            unsigned a[4][4], bb[4][2];                                              \
            _Pragma("unroll")                                                        \
            for (int mt = 0; mt < 4; ++mt)                                           \
                ldsm4(a[mt][0], a[mt][1], a[mt][2], a[mt][3],                        \
                      Xb + (arow + mt * 16) * 40 + kc * 16 + acol);                  \
            _Pragma("unroll")                                                        \
            for (int np = 0; np < 2; ++np)                                           \
                ldsm4(bb[np * 2][0], bb[np * 2][1], bb[np * 2 + 1][0], bb[np * 2 + 1][1], \
                      Wb + (brow + np * 16) * 40 + kc * 16 + bcol);                  \
            _Pragma("unroll")                                                        \
            for (int mt = 0; mt < 4; ++mt)                                           \
                _Pragma("unroll")                                                    \
                for (int nt = 0; nt < 4; ++nt)                                       \
                    mma_f16(ACC[mt][nt], a[mt][0], a[mt][1], a[mt][2], a[mt][3],     \
                            bb[nt][0], bb[nt][1]);                                   \
        }                                                                            \
    }

// Fused QKV GEMM + em preprocessing (v11). grid (6, 160).
__global__ __launch_bounds__(256, 2) void gemm_qkv(
    const __half* __restrict__ X, const __half* __restrict__ Wcat,
    __half* __restrict__ Qd, __half* __restrict__ Kd, __half* __restrict__ Vd,
    const float* __restrict__ edge, const int* __restrict__ mask,
    __half* __restrict__ em)
{
    extern __shared__ __half gsm[];
    const int t = threadIdx.x;

    if (blockIdx.y < 32) {
        const float QNAN = __int_as_float(0x7fc00000);
        int chunk = blockIdx.y * 6 + blockIdx.x;             // 0..191
        for (int j = chunk * 256 + t; j < N_E8; j += 192 * 256) {
            const float4* es = (const float4*)edge + (size_t)j * 2;
            const int4*   ms = (const int4*)mask + (size_t)j * 2;
            float4 e0 = es[0], e1 = es[1];
            int4   m0v = ms[0], m1v = ms[1];
            float4 f0 = make_float4(m0v.x ? e0.x : QNAN, m0v.y ? e0.y : QNAN,
                                    m0v.z ? e0.z : QNAN, m0v.w ? e0.w : QNAN);
            float4 f1 = make_float4(m1v.x ? e1.x : QNAN, m1v.y ? e1.y : QNAN,
                                    m1v.z ? e1.z : QNAN, m1v.w ? e1.w : QNAN);
            ((uint4*)em)[j] = pack8(f0, f1);
        }
        return;
    }

    const int warp = t >> 5, lane = t & 31;
    const int g = lane >> 2, l = lane & 3;
    const int m0 = (blockIdx.y - 32) * 128, n0 = blockIdx.x * 128;
    const int wm = (warp >> 2) * 64, wn = (warp & 3) * 32;
    const int which = blockIdx.x >> 1;
    __half* dst = which == 0 ? Qd : which == 1 ? Kd : Vd;
    const int nloc = n0 & 255;
    const float oscale = (which == 0) ? 0.17677669529663687f * 1.4426950408889634f : 1.0f;

    float acc[4][4][4];
#pragma unroll
    for (int mt = 0; mt < 4; ++mt)
#pragma unroll
        for (int nt = 0; nt < 4; ++nt)
#pragma unroll
            for (int i = 0; i < 4; ++i) acc[mt][nt][i] = 0.f;

    GEMM_BODY(X, Wcat, acc)

#pragma unroll
    for (int mt = 0; mt < 4; ++mt) {
#pragma unroll
        for (int nt = 0; nt < 4; ++nt) {
            int r = m0 + wm + mt * 16 + g;
            int c = nloc + wn + nt * 8 + 2 * l;
            *(__half2*)(dst + (size_t)r * 256 + c) =
                __floats2half2_rn(acc[mt][nt][0] * oscale, acc[mt][nt][1] * oscale);
            *(__half2*)(dst + (size_t)(r + 8) * 256 + c) =
                __floats2half2_rn(acc[mt][nt][2] * oscale, acc[mt][nt][3] * oscale);
        }
    }
}

// Output GEMM: fp32 out, 128x128 tiles, grid (2, 128)
__global__ __launch_bounds__(256, 2) void gemm_out(const __half* __restrict__ X,
                                                   const __half* __restrict__ W,
                                                   float* __restrict__ C)
{
    extern __shared__ __half gsm[];

    const int t = threadIdx.x, warp = t >> 5, lane = t & 31;
    const int g = lane >> 2, l = lane & 3;
    const int m0 = blockIdx.y * 128, n0 = blockIdx.x * 128;
    const int wm = (warp >> 2) * 64, wn = (warp & 3) * 32;

    float acc[4][4][4];
#pragma unroll
    for (int mt = 0; mt < 4; ++mt)
#pragma unroll
        for (int nt = 0; nt < 4; ++nt)
#pragma unroll
            for (int i = 0; i < 4; ++i) acc[mt][nt][i] = 0.f;

    GEMM_BODY(X, W, acc)

#pragma unroll
    for (int mt = 0; mt < 4; ++mt) {
#pragma unroll
        for (int nt = 0; nt < 4; ++nt) {
            int r = m0 + wm + mt * 16 + g;
            int c = n0 + wn + nt * 8 + 2 * l;
            *(float2*)(C + (size_t)r * 256 + c)       = make_float2(acc[mt][nt][0], acc[mt][nt][1]);
            *(float2*)(C + (size_t)(r + 8) * 256 + c) = make_float2(acc[mt][nt][2], acc[mt][nt][3]);
        }
    }
}

// ----------------------------------------------------------------------------
// Attention v15: block = 128 queries x one (b,h), 128 threads (4 warps),
// warp owns 32 q-rows (2 m16 tiles). K/V fragments shared across m-tiles.
// smem: Ks[2][64*40] + Vs[2][64*40] + Es[2][128*72] = 57344 B -> occ 3.
// ----------------------------------------------------------------------------
#define KLDH 40
#define ELDH 72
#define ATT_SMEM_BYTES (10240 + 10240 + 36864)   // 57344

__global__ __launch_bounds__(128, 3) void attn_f16(
    const __half* __restrict__ Qh, const __half* __restrict__ Kh,
    const __half* __restrict__ Vh, const __half* __restrict__ em,
    const float* __restrict__ We, __half* __restrict__ AOh)
{
    extern __shared__ __half dsm[];
    __half* Ks = dsm;             // 2 x 64 x 40
    __half* Vs = dsm + 5120;      // 2 x 64 x 40
    __half* Es = dsm + 10240;     // 2 x 128 x 72 (also Q staging temp)

    const int t = threadIdx.x, warp = t >> 5, lane = t & 31;
    const int g = lane >> 2, l = lane & 3;
    const int bh = blockIdx.y;
    const int b  = bh >> 3, hh = bh & 7;
    const int q0 = blockIdx.x * 128;
    const size_t bN = (size_t)b * NSEQ;
    const float we = We[hh] * 1.4426950408889634f;   // log2 domain

    const int lrow = (lane & 7) + ((lane >> 3) & 1) * 8;   // A/C-frag row-in-16
    const int acol = ((lane >> 4) << 3);
    const int krow = (lane & 7);
    const int kcol = ((lane >> 3) << 3);

    // ---- stage Q (128 x 32, pre-scaled) into Es temp, fragments to registers
#pragma unroll
    for (int i = 0; i < 4; ++i) {
        int idx = t + i * 128;               // 0..511
        int row = idx >> 2, c = idx & 3;
        uint4 v = *(const uint4*)(Qh + ((bN + q0 + row) * DMODEL) + hh * HDIM + c * 8);
        *(uint4*)&Es[row * KLDH + c * 8] = v;
    }
    __syncthreads();

    unsigned qa[2][2][4];
#pragma unroll
    for (int mt = 0; mt < 2; ++mt) {
        int ar = warp * 32 + mt * 16 + lrow;
        ldsm4(qa[mt][0][0], qa[mt][0][1], qa[mt][0][2], qa[mt][0][3], Es + ar * KLDH + acol);
        ldsm4(qa[mt][1][0], qa[mt][1][1], qa[mt][1][2], qa[mt][1][3], Es + ar * KLDH + 16 + acol);
    }
    __syncthreads();

    float mrow[2][2], lrsum[2][2];
    float o[2][4][4];
#pragma unroll
    for (int mt = 0; mt < 2; ++mt) {
        mrow[mt][0] = -1e30f; mrow[mt][1] = -1e30f;
        lrsum[mt][0] = 0.f;   lrsum[mt][1] = 0.f;
#pragma unroll
        for (int nt = 0; nt < 4; ++nt)
#pragma unroll
            for (int i = 0; i < 4; ++i) o[mt][nt][i] = 0.f;
    }

    const int kv_row = t >> 2, kv_c = t & 3;   // 2 iters -> 64 rows x 4 chunks
    const int em_row = t >> 3, em_c = t & 7;   // 8 iters -> 128 rows x 8 chunks

    // prologue: stage tile 0
#pragma unroll
    for (int i = 0; i < 2; ++i) {
        int row = kv_row + i * 32;
        cp16(&Ks[row * KLDH + kv_c * 8], Kh + (bN + row) * DMODEL + hh * HDIM + kv_c * 8);
        cp16(&Vs[row * KLDH + kv_c * 8], Vh + (bN + row) * DMODEL + hh * HDIM + kv_c * 8);
    }
#pragma unroll
    for (int i = 0; i < 8; ++i) {
        int row = em_row + i * 16;
        cp16(&Es[row * ELDH + em_c * 8], em + ((bN + q0 + row) * NSEQ) + em_c * 8);
    }
    CP_COMMIT();

    for (int it = 0; it < 8; ++it) {
        CP_WAIT0();
        __syncthreads();
        if (it < 7) {
            int jt = (it + 1) * 64, buf = (it + 1) & 1;
#pragma unroll
            for (int i = 0; i < 2; ++i) {
                int row = kv_row + i * 32;
                cp16(&Ks[buf * 2560 + row * KLDH + kv_c * 8],
                     Kh + (bN + jt + row) * DMODEL + hh * HDIM + kv_c * 8);
                cp16(&Vs[buf * 2560 + row * KLDH + kv_c * 8],
                     Vh + (bN + jt + row) * DMODEL + hh * HDIM + kv_c * 8);
            }
#pragma unroll
            for (int i = 0; i < 8; ++i) {
                int row = em_row + i * 16;
                cp16(&Es[buf * 9216 + row * ELDH + em_c * 8],
                     em + ((bN + q0 + row) * NSEQ) + jt + em_c * 8);
            }
        }
        CP_COMMIT();

        const __half* Kb = Ks + (it & 1) * 2560;
        const __half* Vb = Vs + (it & 1) * 2560;
        const __half* Eb = Es + (it & 1) * 9216;

        // ---- S = Q K^T : K fragments shared across both m-tiles
        float s[2][8][4];
#pragma unroll
        for (int mt = 0; mt < 2; ++mt)
#pragma unroll
            for (int nt = 0; nt < 8; ++nt)
#pragma unroll
                for (int i = 0; i < 4; ++i) s[mt][nt][i] = 0.f;

#pragma unroll
        for (int nt = 0; nt < 8; ++nt) {
            unsigned b0, b1, b2, b3;
            ldsm4(b0, b1, b2, b3, Kb + (8 * nt + krow) * KLDH + kcol);
            mma_f16(s[0][nt], qa[0][0][0], qa[0][0][1], qa[0][0][2], qa[0][0][3], b0, b1);
            mma_f16(s[0][nt], qa[0][1][0], qa[0][1][1], qa[0][1][2], qa[0][1][3], b2, b3);
            mma_f16(s[1][nt], qa[1][0][0], qa[1][0][1], qa[1][0][2], qa[1][0][3], b0, b1);
            mma_f16(s[1][nt], qa[1][1][0], qa[1][1][1], qa[1][1][2], qa[1][1][3], b2, b3);
        }

        // ---- bias + mask(NaN) + online softmax per m-tile
        unsigned ph[2][8][2];
#pragma unroll
        for (int mt = 0; mt < 2; ++mt) {
            const int ar = warp * 32 + mt * 16 + lrow;
            float mn0 = mrow[mt][0], mn1 = mrow[mt][1];
#pragma unroll
            for (int i = 0; i < 4; ++i) {
                unsigned e0, e1, e2, e3;
                ldsm4(e0, e1, e2, e3, Eb + ar * ELDH + i * 16 + acol);
                float2 f0 = __half22float2(*(__half2*)&e0);
                float2 f1 = __half22float2(*(__half2*)&e1);
                float2 f2 = __half22float2(*(__half2*)&e2);
                float2 f3 = __half22float2(*(__half2*)&e3);
                int n0i = 2 * i, n1i = 2 * i + 1;
                s[mt][n0i][0] = fmaxf(fmaf(we, f0.x, s[mt][n0i][0]), -1e30f);
                s[mt][n0i][1] = fmaxf(fmaf(we, f0.y, s[mt][n0i][1]), -1e30f);
                s[mt][n0i][2] = fmaxf(fmaf(we, f1.x, s[mt][n0i][2]), -1e30f);
                s[mt][n0i][3] = fmaxf(fmaf(we, f1.y, s[mt][n0i][3]), -1e30f);
                s[mt][n1i][0] = fmaxf(fmaf(we, f2.x, s[mt][n1i][0]), -1e30f);
                s[mt][n1i][1] = fmaxf(fmaf(we, f2.y, s[mt][n1i][1]), -1e30f);
                s[mt][n1i][2] = fmaxf(fmaf(we, f3.x, s[mt][n1i][2]), -1e30f);
                s[mt][n1i][3] = fmaxf(fmaf(we, f3.y, s[mt][n1i][3]), -1e30f);
                mn0 = fmaxf(mn0, fmaxf(fmaxf(s[mt][n0i][0], s[mt][n0i][1]),
                                       fmaxf(s[mt][n1i][0], s[mt][n1i][1])));
                mn1 = fmaxf(mn1, fmaxf(fmaxf(s[mt][n0i][2], s[mt][n0i][3]),
                                       fmaxf(s[mt][n1i][2], s[mt][n1i][3])));
            }
            mn0 = fmaxf(mn0, __shfl_xor_sync(0xffffffff, mn0, 1));
            mn0 = fmaxf(mn0, __shfl_xor_sync(0xffffffff, mn0, 2));
            mn1 = fmaxf(mn1, __shfl_xor_sync(0xffffffff, mn1, 1));
            mn1 = fmaxf(mn1, __shfl_xor_sync(0xffffffff, mn1, 2));

            float corr0 = exp2f(mrow[mt][0] - mn0);
            float corr1 = exp2f(mrow[mt][1] - mn1);
            mrow[mt][0] = mn0; mrow[mt][1] = mn1;

            float ps0 = 0.f, ps1 = 0.f;
#pragma unroll
            for (int nt = 0; nt < 8; ++nt) {
                __half2 x01 = __floats2half2_rn(s[mt][nt][0] - mn0, s[mt][nt][1] - mn0);
                __half2 x23 = __floats2half2_rn(s[mt][nt][2] - mn1, s[mt][nt][3] - mn1);
                __half2 p01 = h2exp2(x01);
                __half2 p23 = h2exp2(x23);
                ph[mt][nt][0] = *(unsigned*)&p01;
                ph[mt][nt][1] = *(unsigned*)&p23;
                float2 f01 = __half22float2(p01);
                float2 f23 = __half22float2(p23);
                ps0 += f01.x + f01.y;
                ps1 += f23.x + f23.y;
            }
            ps0 += __shfl_xor_sync(0xffffffff, ps0, 1);
            ps0 += __shfl_xor_sync(0xffffffff, ps0, 2);
            ps1 += __shfl_xor_sync(0xffffffff, ps1, 1);
            ps1 += __shfl_xor_sync(0xffffffff, ps1, 2);
            lrsum[mt][0] = lrsum[mt][0] * corr0 + ps0;
            lrsum[mt][1] = lrsum[mt][1] * corr1 + ps1;

#pragma unroll
            for (int nt = 0; nt < 4; ++nt) {
                o[mt][nt][0] *= corr0; o[mt][nt][1] *= corr0;
                o[mt][nt][2] *= corr1; o[mt][nt][3] *= corr1;
            }
        }

        // ---- O += P @ V : V fragments shared across both m-tiles
        const int vkey = ((lane >> 3) & 1) << 3;
        const int vd   = ((lane >> 4) & 1) << 3;
        const int vr   = lane & 7;
#pragma unroll
        for (int kc = 0; kc < 4; ++kc) {
            unsigned v0, v1, v2, v3, v4, v5, v6, v7;
            const __half* basep = Vb + (16 * kc + vkey + vr) * KLDH + vd;
            ldsm4t(v0, v1, v2, v3, basep);
            ldsm4t(v4, v5, v6, v7, basep + 16);
#pragma unroll
            for (int mt = 0; mt < 2; ++mt) {
                unsigned a0 = ph[mt][2 * kc][0];
                unsigned a1 = ph[mt][2 * kc][1];
                unsigned a2 = ph[mt][2 * kc + 1][0];
                unsigned a3 = ph[mt][2 * kc + 1][1];
                mma_f16(o[mt][0], a0, a1, a2, a3, v0, v1);
                mma_f16(o[mt][1], a0, a1, a2, a3, v2, v3);
                mma_f16(o[mt][2], a0, a1, a2, a3, v4, v5);
                mma_f16(o[mt][3], a0, a1, a2, a3, v6, v7);
            }
        }
    }

    // ---- write output (fp16)
#pragma unroll
    for (int mt = 0; mt < 2; ++mt) {
        const float inv0 = 1.0f / lrsum[mt][0];
        const float inv1 = 1.0f / lrsum[mt][1];
        const int r = q0 + warp * 32 + mt * 16 + g;
#pragma unroll
        for (int nt = 0; nt < 4; ++nt) {
            int c = hh * HDIM + nt * 8 + 2 * l;
            *(__half2*)(AOh + (bN + r) * DMODEL + c) =
                __floats2half2_rn(o[mt][nt][0] * inv0, o[mt][nt][1] * inv0);
            *(__half2*)(AOh + (bN + r + 8) * DMODEL + c) =
                __floats2half2_rn(o[mt][nt][2] * inv1, o[mt][nt][3] * inv1);
        }
    }
}

// ----------------------------------------------------------------------------
// launch
// ----------------------------------------------------------------------------
extern "C" void kernel_launch(void* const* d_in, const int* in_sizes, int n_in,
                              void* d_out, int out_size)
{
    const float* h    = (const float*)d_in[0];
    const float* edge = (const float*)d_in[1];
    const int*   mask = (const int*)  d_in[2];
    const float* Wq   = (const float*)d_in[3];
    const float* Wk   = (const float*)d_in[4];
    const float* Wv   = (const float*)d_in[5];
    const float* We   = (const float*)d_in[6];
    const float* Wo   = (const float*)d_in[7];
    float* out = (float*)d_out;

    __half *h16, *q16, *k16, *v16, *ao16, *emh, *w16;
    cudaGetSymbolAddress((void**)&h16,  g_h16);
    cudaGetSymbolAddress((void**)&q16,  g_q16);
    cudaGetSymbolAddress((void**)&k16,  g_k16);
    cudaGetSymbolAddress((void**)&v16,  g_v16);
    cudaGetSymbolAddress((void**)&ao16, g_ao16);
    cudaGetSymbolAddress((void**)&emh,  g_em);
    cudaGetSymbolAddress((void**)&w16,  g_w16);

    cudaFuncSetAttribute(gemm_qkv, cudaFuncAttributeMaxDynamicSharedMemorySize, GEMM_SMEM_BYTES);
    cudaFuncSetAttribute(gemm_out, cudaFuncAttributeMaxDynamicSharedMemorySize, GEMM_SMEM_BYTES);
    cudaFuncSetAttribute(attn_f16, cudaFuncAttributeMaxDynamicSharedMemorySize, ATT_SMEM_BYTES);

    prep_hw<<<(N_HW8 + 255) / 256, 256>>>(h, Wq, Wk, Wv, Wo, h16, w16);

    // by<32: em-prep streaming blocks (first); by>=32: 128x128 gemm tiles
    gemm_qkv<<<dim3(6, 160), 256, GEMM_SMEM_BYTES>>>(h16, w16, q16, k16, v16, edge, mask, emh);

    attn_f16<<<dim3(NSEQ / 128, BATCH * NHEAD), 128, ATT_SMEM_BYTES>>>(q16, k16, v16, emh, We, ao16);

    gemm_out<<<dim3(2, MROWS / 128), 256, GEMM_SMEM_BYTES>>>(ao16, w16 + 3 * DMODEL * DMODEL, out);
}